// round 1
// baseline (speedup 1.0000x reference)
#include <cuda_runtime.h>
#include <math.h>

#define NN 4096
#define ALPHA 0.2f

__device__ __forceinline__ float lrelu(float v){ return v >= 0.f ? v : ALPHA * v; }

// ---------------- scratch arenas (device globals; no allocation) -------------
// float arena layout (offsets in floats)
#define OFF_HIN   0L          // 4096*512   = 2097152
#define OFF_WH    2097152L    // 4*4096*256 = 4194304
#define OFF_H1    6291456L    // 4*4096*256 = 4194304
#define OFF_HCAT  10485760L   // 4096*1024  = 4194304
#define OFF_OWH   14680064L   // 4096*64    = 262144
#define OFF_HO0   14942208L   // 4096*64    = 262144
#define OFF_WHC   15204352L   // 4096
#define OFF_HOUT  15208448L   // 4096
#define OFF_S1    15212544L   // 4096
#define OFF_S2    15216640L   // 4096
#define OFF_M     15220736L   // 16 (scalar, padded)
#define OFF_DV    15220752L   // 4096
#define FARENA_SZ 15230000L

// int arena layout
#define OFF_CNT   0           // 4096
#define OFF_RP    4096        // 4097
#define OFF_CI    8200        // edge column indices (~664K expected)
#define IARENA_SZ 2200000

__device__ float g_farena[FARENA_SZ];
__device__ int   g_iarena[IARENA_SZ];

// ---------------- CSR construction ----------------
__global__ void k_count(const float* __restrict__ adj, int* __restrict__ cnt) {
    int row = blockIdx.x, tid = threadIdx.x;
    const float4* p = reinterpret_cast<const float4*>(adj + (long)row * NN);
    int c = 0;
    for (int i = tid; i < NN / 4; i += 256) {
        float4 v = p[i];
        c += (v.x > 0.f) + (v.y > 0.f) + (v.z > 0.f) + (v.w > 0.f);
    }
    __shared__ int s[256];
    s[tid] = c; __syncthreads();
    for (int st = 128; st; st >>= 1) { if (tid < st) s[tid] += s[tid + st]; __syncthreads(); }
    if (tid == 0) cnt[row] = s[0];
}

__global__ void k_scan(const int* __restrict__ cnt, int* __restrict__ rp) {
    __shared__ int s[1024];
    int t = threadIdx.x;
    int v[4]; int loc = 0;
#pragma unroll
    for (int k = 0; k < 4; k++) { v[k] = cnt[t * 4 + k]; loc += v[k]; }
    s[t] = loc; __syncthreads();
    for (int off = 1; off < 1024; off <<= 1) {
        int add = (t >= off) ? s[t - off] : 0;
        __syncthreads();
        s[t] += add;
        __syncthreads();
    }
    int run = (t == 0) ? 0 : s[t - 1];
#pragma unroll
    for (int k = 0; k < 4; k++) { rp[t * 4 + k] = run; run += v[k]; }
    if (t == 1023) rp[NN] = run;
}

__global__ void k_fill(const float* __restrict__ adj, const int* __restrict__ rp,
                       int* __restrict__ ci) {
    int row = blockIdx.x, tid = threadIdx.x;
    const float4* p = reinterpret_cast<const float4*>(adj + (long)row * NN);
    float4 vv[4]; int c = 0;
#pragma unroll
    for (int k = 0; k < 4; k++) {
        vv[k] = p[tid + k * 256];
        c += (vv[k].x > 0.f) + (vv[k].y > 0.f) + (vv[k].z > 0.f) + (vv[k].w > 0.f);
    }
    __shared__ int s[256];
    s[tid] = c; __syncthreads();
    for (int off = 1; off < 256; off <<= 1) {
        int add = (tid >= off) ? s[tid - off] : 0;
        __syncthreads();
        s[tid] += add;
        __syncthreads();
    }
    int pos = rp[row] + ((tid == 0) ? 0 : s[tid - 1]);
#pragma unroll
    for (int k = 0; k < 4; k++) {
        int col = (tid + k * 256) * 4;
        if (vv[k].x > 0.f) ci[pos++] = col;
        if (vv[k].y > 0.f) ci[pos++] = col + 1;
        if (vv[k].z > 0.f) ci[pos++] = col + 2;
        if (vv[k].w > 0.f) ci[pos++] = col + 3;
    }
}

// ---------------- misc elementwise / reductions ----------------
__global__ void k_rowsum(const float* __restrict__ sm, float* __restrict__ dv) {
    int row = blockIdx.x, tid = threadIdx.x;
    const float4* p = reinterpret_cast<const float4*>(sm + (long)row * NN);
    float acc = 0.f;
    for (int i = tid; i < NN / 4; i += 256) { float4 v = p[i]; acc += v.x + v.y + v.z + v.w; }
    __shared__ float s[256];
    s[tid] = acc; __syncthreads();
    for (int st = 128; st; st >>= 1) { if (tid < st) s[tid] += s[tid + st]; __syncthreads(); }
    if (tid == 0) dv[row] = s[0];
}

__global__ void k_merge(const float* __restrict__ x, const int* __restrict__ obs,
                        const float* __restrict__ theta, float* __restrict__ hin) {
    long i = (long)blockIdx.x * blockDim.x + threadIdx.x;  // over 4096*512
    int row = (int)(i >> 9);
    int f = (int)(i & 511);
    float add = (obs[row] == 1) ? theta[f] : 0.f;
    hin[i] = x[i] + add;
}

// s1 = Wh @ a[:fout], s2 = Wh @ a[fout:]   (one warp per row)
__global__ void k_s(const float* __restrict__ Wh, const float* __restrict__ a, int fout,
                    float* __restrict__ s1, float* __restrict__ s2) {
    int gw = (blockIdx.x * blockDim.x + threadIdx.x) >> 5;
    int lane = threadIdx.x & 31;
    if (gw >= NN) return;
    const float* row = Wh + (long)gw * fout;
    float d1 = 0.f, d2 = 0.f;
    for (int f = lane; f < fout; f += 32) {
        float v = row[f];
        d1 += v * a[f];
        d2 += v * a[fout + f];
    }
    for (int o = 16; o; o >>= 1) {
        d1 += __shfl_xor_sync(0xFFFFFFFFu, d1, o);
        d2 += __shfl_xor_sync(0xFFFFFFFFu, d2, o);
    }
    if (lane == 0) { s1[gw] = d1; s2[gw] = d2; }
}

// M = leaky(max(s1) + max(s2))  — global softmax shift (valid: leaky is monotone)
__global__ void k_max(const float* __restrict__ s1, const float* __restrict__ s2,
                      float* __restrict__ Mp) {
    __shared__ float m1s[512], m2s[512];
    int t = threadIdx.x;
    float m1 = -1e30f, m2 = -1e30f;
    for (int i = t; i < NN; i += 512) { m1 = fmaxf(m1, s1[i]); m2 = fmaxf(m2, s2[i]); }
    m1s[t] = m1; m2s[t] = m2; __syncthreads();
    for (int s = 256; s; s >>= 1) {
        if (t < s) { m1s[t] = fmaxf(m1s[t], m1s[t + s]); m2s[t] = fmaxf(m2s[t], m2s[t + s]); }
        __syncthreads();
    }
    if (t == 0) Mp[0] = lrelu(m1s[0] + m2s[0]);
}

// ---------------- sparse attention aggregation ----------------
// out[i,:] = (sum_{j in N(i)} w_ij * Wh[j,:]) / Z_i,  w_ij = exp(leaky(s1_i+s2_j)-M)
template <int FOUT, bool DOELU>
__global__ void k_agg(const float* __restrict__ Wh, const float* __restrict__ s1,
                      const float* __restrict__ s2, const float* __restrict__ Mp,
                      const int* __restrict__ rp, const int* __restrict__ ci,
                      float* __restrict__ out, int ostride) {
    constexpr int TX = FOUT / 4;
    constexpr int TY = 256 / TX;
    constexpr int CH = 256;
    int row = blockIdx.x;
    int tid = threadIdx.x;
    int tx = tid % TX, ty = tid / TX;

    __shared__ float sw[CH];
    __shared__ int sj[CH];
    __shared__ float4 sacc[256];
    __shared__ float sz[256];

    float s1i = s1[row];
    float M = Mp[0];
    int rs = rp[row], re = rp[row + 1];

    float4 acc = make_float4(0.f, 0.f, 0.f, 0.f);
    float z = 0.f;

    for (int base = rs; base < re; base += CH) {
        int n = min(CH, re - base);
        __syncthreads();
        for (int t = tid; t < n; t += 256) {
            int j = ci[base + t];
            sj[t] = j;
            float e = lrelu(s1i + s2[j]) - M;
            float w = __expf(e);
            sw[t] = w;
            z += w;
        }
        __syncthreads();
        for (int t = ty; t < n; t += TY) {
            float w = sw[t];
            const float4* p = reinterpret_cast<const float4*>(Wh + (long)sj[t] * FOUT);
            float4 v = p[tx];
            acc.x += w * v.x; acc.y += w * v.y; acc.z += w * v.z; acc.w += w * v.w;
        }
    }
    sacc[tid] = acc; sz[tid] = z; __syncthreads();
    for (int s = 128; s; s >>= 1) { if (tid < s) sz[tid] += sz[tid + s]; __syncthreads(); }
    float Z = sz[0];
    if (ty == 0) {
        float4 a = sacc[tx];
#pragma unroll
        for (int yy = 1; yy < TY; yy++) {
            float4 b = sacc[yy * TX + tx];
            a.x += b.x; a.y += b.y; a.z += b.z; a.w += b.w;
        }
        float inv = 1.0f / Z;
        float o[4] = { a.x * inv, a.y * inv, a.z * inv, a.w * inv };
        if (DOELU) {
#pragma unroll
            for (int k = 0; k < 4; k++) o[k] = o[k] > 0.f ? o[k] : expm1f(o[k]);
        }
        *reinterpret_cast<float4*>(out + (long)row * ostride + tx * 4) =
            make_float4(o[0], o[1], o[2], o[3]);
    }
}

// FOUT == 1 aggregation (final output attention layer)
__global__ void k_agg1(const float* __restrict__ whc, const float* __restrict__ s1,
                       const float* __restrict__ s2, const float* __restrict__ Mp,
                       const int* __restrict__ rp, const int* __restrict__ ci,
                       float* __restrict__ out) {
    int row = blockIdx.x, tid = threadIdx.x;
    __shared__ float sa[256], szz[256];
    float s1i = s1[row], M = Mp[0];
    int rs = rp[row], re = rp[row + 1];
    float acc = 0.f, z = 0.f;
    for (int e = rs + tid; e < re; e += 256) {
        int j = ci[e];
        float t = lrelu(s1i + s2[j]) - M;
        float w = __expf(t);
        z += w;
        acc += w * whc[j];
    }
    sa[tid] = acc; szz[tid] = z; __syncthreads();
    for (int s = 128; s; s >>= 1) {
        if (tid < s) { sa[tid] += sa[tid + s]; szz[tid] += szz[tid + s]; }
        __syncthreads();
    }
    if (tid == 0) out[row] = sa[0] / szz[0];
}

// out-layer-1 projection: whc[i] = dot(ho0[i,:64], Wo1);  s1=whc*ao1[0]; s2=whc*ao1[1]
__global__ void k_out1s(const float* __restrict__ h, const float* __restrict__ Wo1,
                        const float* __restrict__ ao1, float* __restrict__ whc,
                        float* __restrict__ s1, float* __restrict__ s2) {
    int gw = (blockIdx.x * blockDim.x + threadIdx.x) >> 5;
    int lane = threadIdx.x & 31;
    if (gw >= NN) return;
    float d = 0.f;
    for (int f = lane; f < 64; f += 32) d += h[(long)gw * 64 + f] * Wo1[f];
    for (int o = 16; o; o >>= 1) d += __shfl_xor_sync(0xFFFFFFFFu, d, o);
    if (lane == 0) { whc[gw] = d; s1[gw] = d * ao1[0]; s2[gw] = d * ao1[1]; }
}

// ---------------- dense SGEMM: C = A @ B  (row-major, batched) ----------------
// 128x128 tile, BK=8, 256 threads, 8x8 microtile
__global__ void __launch_bounds__(256) k_sgemm(
    const float* __restrict__ A, const float* __restrict__ B, float* __restrict__ C,
    int M, int N, int K, long sA, long sB, long sC) {
    A += (long)blockIdx.z * sA;
    B += (long)blockIdx.z * sB;
    C += (long)blockIdx.z * sC;
    __shared__ __align__(16) float As[8][128];
    __shared__ __align__(16) float Bs[8][128];
    int tid = threadIdx.x;
    int m0 = blockIdx.y * 128, n0 = blockIdx.x * 128;
    int arow = tid >> 1;
    int acol = (tid & 1) * 4;
    int brow = tid >> 5;
    int bcol = (tid & 31) * 4;
    int tx = tid & 15, ty = tid >> 4;
    float acc[8][8] = {};
    for (int kk = 0; kk < K; kk += 8) {
        float4 av = *reinterpret_cast<const float4*>(A + (long)(m0 + arow) * K + kk + acol);
        As[acol + 0][arow] = av.x;
        As[acol + 1][arow] = av.y;
        As[acol + 2][arow] = av.z;
        As[acol + 3][arow] = av.w;
        float4 bv = make_float4(0.f, 0.f, 0.f, 0.f);
        if (n0 + bcol < N)
            bv = *reinterpret_cast<const float4*>(B + (long)(kk + brow) * N + n0 + bcol);
        *reinterpret_cast<float4*>(&Bs[brow][bcol]) = bv;
        __syncthreads();
#pragma unroll
        for (int k = 0; k < 8; k++) {
            float4 a0 = *reinterpret_cast<const float4*>(&As[k][ty * 8]);
            float4 a1 = *reinterpret_cast<const float4*>(&As[k][ty * 8 + 4]);
            float4 b0 = *reinterpret_cast<const float4*>(&Bs[k][tx * 8]);
            float4 b1 = *reinterpret_cast<const float4*>(&Bs[k][tx * 8 + 4]);
            float am[8] = { a0.x, a0.y, a0.z, a0.w, a1.x, a1.y, a1.z, a1.w };
            float bn[8] = { b0.x, b0.y, b0.z, b0.w, b1.x, b1.y, b1.z, b1.w };
#pragma unroll
            for (int i = 0; i < 8; i++)
#pragma unroll
                for (int j = 0; j < 8; j++) acc[i][j] += am[i] * bn[j];
        }
        __syncthreads();
    }
#pragma unroll
    for (int i = 0; i < 8; i++) {
        int r = m0 + ty * 8 + i;
#pragma unroll
        for (int j = 0; j < 8; j += 4) {
            int c = n0 + tx * 8 + j;
            if (c < N)
                *reinterpret_cast<float4*>(C + (long)r * N + c) =
                    make_float4(acc[i][j], acc[i][j + 1], acc[i][j + 2], acc[i][j + 3]);
        }
    }
}

// ---------------- final degree MLP ----------------
__global__ void k_mlp(const float* __restrict__ hout, const float* __restrict__ dv,
                      const float* __restrict__ dW, const float* __restrict__ dW0,
                      const float* __restrict__ dW1, const float* __restrict__ dW01,
                      const float* __restrict__ dW2, const float* __restrict__ dW02,
                      const float* __restrict__ dV, const float* __restrict__ dV0,
                      float* __restrict__ out) {
    int i = blockIdx.x * blockDim.x + threadIdx.x;
    if (i >= NN) return;
    float hv = hout[i];
    float x0 = hv > 0.f ? hv : expm1f(hv);  // elu
    float x1 = dv[i];
    float h0[10];
#pragma unroll
    for (int k = 0; k < 10; k++)
        h0[k] = lrelu(x0 * dW[k] + x1 * dW[10 + k] + dW0[k]);
    float h1[20];
#pragma unroll
    for (int k = 0; k < 20; k++) {
        float t = dW01[k];
#pragma unroll
        for (int j = 0; j < 10; j++) t += h0[j] * dW1[j * 20 + k];
        h1[k] = lrelu(t);
    }
    float h2[10];
#pragma unroll
    for (int k = 0; k < 10; k++) {
        float t = dW02[k];
#pragma unroll
        for (int j = 0; j < 20; j++) t += h1[j] * dW2[j * 10 + k];
        h2[k] = lrelu(t);
    }
    float o = dV0[0];
#pragma unroll
    for (int j = 0; j < 10; j++) o += h2[j] * dV[j];
    out[i] = lrelu(o);
}

// ---------------- launch ----------------
extern "C" void kernel_launch(void* const* d_in, const int* in_sizes, int n_in,
                              void* d_out, int out_size) {
    const float* x     = (const float*)d_in[0];
    const float* adj   = (const float*)d_in[1];
    const int*   obs   = (const int*)d_in[2];
    const float* s_mat = (const float*)d_in[3];
    const float* theta = (const float*)d_in[4];
    const float* Wh0   = (const float*)d_in[5];
    const float* ah0   = (const float*)d_in[6];
    const float* Wh1   = (const float*)d_in[7];
    const float* ah1   = (const float*)d_in[8];
    const float* Wo0   = (const float*)d_in[9];
    const float* ao0   = (const float*)d_in[10];
    const float* Wo1   = (const float*)d_in[11];
    const float* ao1   = (const float*)d_in[12];
    const float* dW    = (const float*)d_in[13];
    const float* dW0   = (const float*)d_in[14];
    const float* dW1   = (const float*)d_in[15];
    const float* dW01  = (const float*)d_in[16];
    const float* dW2   = (const float*)d_in[17];
    const float* dW02  = (const float*)d_in[18];
    const float* dV    = (const float*)d_in[19];
    const float* dV0   = (const float*)d_in[20];
    float* out = (float*)d_out;

    float* fa = nullptr;
    int*   ia = nullptr;
    cudaGetSymbolAddress((void**)&fa, g_farena);
    cudaGetSymbolAddress((void**)&ia, g_iarena);

    float* hin  = fa + OFF_HIN;
    float* Wh   = fa + OFF_WH;
    float* h1b  = fa + OFF_H1;
    float* hcat = fa + OFF_HCAT;
    float* oWh  = fa + OFF_OWH;
    float* ho0  = fa + OFF_HO0;
    float* whc  = fa + OFF_WHC;
    float* hout = fa + OFF_HOUT;
    float* s1   = fa + OFF_S1;
    float* s2   = fa + OFF_S2;
    float* Mp   = fa + OFF_M;
    float* dv   = fa + OFF_DV;
    int* cnt = ia + OFF_CNT;
    int* rp  = ia + OFF_RP;
    int* ci  = ia + OFF_CI;

    const long NM = (long)NN * 256;

    // CSR of adjacency (shared by all 10 layers)
    k_count<<<NN, 256>>>(adj, cnt);
    k_scan<<<1, 1024>>>(cnt, rp);
    k_fill<<<NN, 256>>>(adj, rp, ci);

    // degree vector from s_mat
    k_rowsum<<<NN, 256>>>(s_mat, dv);

    // h_in = x + seed * theta
    k_merge<<<(NN * 512) / 256, 256>>>(x, obs, theta, hin);

    // ---- head layer 0 (batched over 4 heads): Wh = h_in @ Wh0[h] ----
    k_sgemm<<<dim3(2, 32, 4), 256>>>(hin, Wh0, Wh, NN, 256, 512, 0L, 512L * 256, NM);
    for (int h = 0; h < 4; h++) {
        k_s<<<512, 256>>>(Wh + h * NM, ah0 + h * 512, 256, s1, s2);
        k_max<<<1, 512>>>(s1, s2, Mp);
        k_agg<256, true><<<NN, 256>>>(Wh + h * NM, s1, s2, Mp, rp, ci, h1b + h * NM, 256);
    }

    // ---- head layer 1: Wh = h1 @ Wh1[h]; output written into hcat columns ----
    k_sgemm<<<dim3(2, 32, 4), 256>>>(h1b, Wh1, Wh, NN, 256, 256, NM, 256L * 256, NM);
    for (int h = 0; h < 4; h++) {
        k_s<<<512, 256>>>(Wh + h * NM, ah1 + h * 512, 256, s1, s2);
        k_max<<<1, 512>>>(s1, s2, Mp);
        k_agg<256, true><<<NN, 256>>>(Wh + h * NM, s1, s2, Mp, rp, ci, hcat + h * 256, 1024);
    }

    // ---- output layer 0: [4096,1024] @ [1024,64], concat=False (no elu) ----
    k_sgemm<<<dim3(1, 32, 1), 256>>>(hcat, Wo0, oWh, NN, 64, 1024, 0L, 0L, 0L);
    k_s<<<512, 256>>>(oWh, ao0, 64, s1, s2);
    k_max<<<1, 512>>>(s1, s2, Mp);
    k_agg<64, false><<<NN, 256>>>(oWh, s1, s2, Mp, rp, ci, ho0, 64);

    // ---- output layer 1: Fout = 1 ----
    k_out1s<<<512, 256>>>(ho0, Wo1, ao1, whc, s1, s2);
    k_max<<<1, 512>>>(s1, s2, Mp);
    k_agg1<<<NN, 256>>>(whc, s1, s2, Mp, rp, ci, hout);

    // ---- elu + degree MLP ----
    k_mlp<<<16, 256>>>(hout, dv, dW, dW0, dW1, dW01, dW2, dW02, dV, dV0, out);
}

// round 2
// speedup vs baseline: 1.0315x; 1.0315x over previous
#include <cuda_runtime.h>
#include <cuda_bf16.h>
#include <math.h>

#define NN 4096
#define ALPHA 0.2f

__device__ __forceinline__ float lrelu(float v){ return v >= 0.f ? v : ALPHA * v; }

// ---------------- scratch arenas (device globals; no allocation) -------------
#define OFF_HIN   0L          // 4096*512
#define OFF_WH    2097152L    // 4*4096*256
#define OFF_H1    6291456L    // 4*4096*256
#define OFF_HCAT  10485760L   // 4096*1024
#define OFF_OWH   14680064L   // 4096*64
#define OFF_HO0   14942208L   // 4096*64
#define OFF_WHC   15204352L   // 4096
#define OFF_HOUT  15208448L   // 4096
#define OFF_S1    15212544L   // 4*4096
#define OFF_S2    15228928L   // 4*4096
#define OFF_M     15245312L   // 16
#define OFF_DV    15245328L   // 4096
#define OFF_WHB   15249424L   // bf16 Wh: 4*4096*256 bf16 = 2097152 floats
#define FARENA_SZ 17350000L

#define OFF_CNT   0
#define OFF_RP    4096
#define OFF_CI    8200
#define IARENA_SZ 2200000

__device__ float g_farena[FARENA_SZ];
__device__ int   g_iarena[IARENA_SZ];

// ---------------- CSR construction ----------------
__global__ void k_count(const float* __restrict__ adj, int* __restrict__ cnt) {
    int row = blockIdx.x, tid = threadIdx.x;
    const float4* p = reinterpret_cast<const float4*>(adj + (long)row * NN);
    int c = 0;
    for (int i = tid; i < NN / 4; i += 256) {
        float4 v = p[i];
        c += (v.x > 0.f) + (v.y > 0.f) + (v.z > 0.f) + (v.w > 0.f);
    }
    __shared__ int s[256];
    s[tid] = c; __syncthreads();
    for (int st = 128; st; st >>= 1) { if (tid < st) s[tid] += s[tid + st]; __syncthreads(); }
    if (tid == 0) cnt[row] = s[0];
}

__global__ void k_scan(const int* __restrict__ cnt, int* __restrict__ rp) {
    __shared__ int s[1024];
    int t = threadIdx.x;
    int v[4]; int loc = 0;
#pragma unroll
    for (int k = 0; k < 4; k++) { v[k] = cnt[t * 4 + k]; loc += v[k]; }
    s[t] = loc; __syncthreads();
    for (int off = 1; off < 1024; off <<= 1) {
        int add = (t >= off) ? s[t - off] : 0;
        __syncthreads();
        s[t] += add;
        __syncthreads();
    }
    int run = (t == 0) ? 0 : s[t - 1];
#pragma unroll
    for (int k = 0; k < 4; k++) { rp[t * 4 + k] = run; run += v[k]; }
    if (t == 1023) rp[NN] = run;
}

__global__ void k_fill(const float* __restrict__ adj, const int* __restrict__ rp,
                       int* __restrict__ ci) {
    int row = blockIdx.x, tid = threadIdx.x;
    const float4* p = reinterpret_cast<const float4*>(adj + (long)row * NN);
    float4 vv[4]; int c = 0;
#pragma unroll
    for (int k = 0; k < 4; k++) {
        vv[k] = p[tid + k * 256];
        c += (vv[k].x > 0.f) + (vv[k].y > 0.f) + (vv[k].z > 0.f) + (vv[k].w > 0.f);
    }
    __shared__ int s[256];
    s[tid] = c; __syncthreads();
    for (int off = 1; off < 256; off <<= 1) {
        int add = (tid >= off) ? s[tid - off] : 0;
        __syncthreads();
        s[tid] += add;
        __syncthreads();
    }
    int pos = rp[row] + ((tid == 0) ? 0 : s[tid - 1]);
#pragma unroll
    for (int k = 0; k < 4; k++) {
        int col = (tid + k * 256) * 4;
        if (vv[k].x > 0.f) ci[pos++] = col;
        if (vv[k].y > 0.f) ci[pos++] = col + 1;
        if (vv[k].z > 0.f) ci[pos++] = col + 2;
        if (vv[k].w > 0.f) ci[pos++] = col + 3;
    }
}

// ---------------- misc ----------------
__global__ void k_rowsum(const float* __restrict__ sm, float* __restrict__ dv) {
    int row = blockIdx.x, tid = threadIdx.x;
    const float4* p = reinterpret_cast<const float4*>(sm + (long)row * NN);
    float acc = 0.f;
    for (int i = tid; i < NN / 4; i += 256) { float4 v = p[i]; acc += v.x + v.y + v.z + v.w; }
    __shared__ float s[256];
    s[tid] = acc; __syncthreads();
    for (int st = 128; st; st >>= 1) { if (tid < st) s[tid] += s[tid + st]; __syncthreads(); }
    if (tid == 0) dv[row] = s[0];
}

__global__ void k_merge(const float* __restrict__ x, const int* __restrict__ obs,
                        const float* __restrict__ theta, float* __restrict__ hin) {
    long i = (long)blockIdx.x * blockDim.x + threadIdx.x;
    int row = (int)(i >> 9);
    int f = (int)(i & 511);
    float add = (obs[row] == 1) ? theta[f] : 0.f;
    hin[i] = x[i] + add;
}

// s for a single matrix (out layer 0, fout=64)
__global__ void k_s(const float* __restrict__ Wh, const float* __restrict__ a, int fout,
                    float* __restrict__ s1, float* __restrict__ s2) {
    int gw = (blockIdx.x * blockDim.x + threadIdx.x) >> 5;
    int lane = threadIdx.x & 31;
    if (gw >= NN) return;
    const float* row = Wh + (long)gw * fout;
    float d1 = 0.f, d2 = 0.f;
    for (int f = lane; f < fout; f += 32) {
        float v = row[f];
        d1 += v * a[f];
        d2 += v * a[fout + f];
    }
    for (int o = 16; o; o >>= 1) {
        d1 += __shfl_xor_sync(0xFFFFFFFFu, d1, o);
        d2 += __shfl_xor_sync(0xFFFFFFFFu, d2, o);
    }
    if (lane == 0) { s1[gw] = d1; s2[gw] = d2; }
}

// s for all 4 heads at once (fout=256, heads contiguous in Wh)
__global__ void k_s4(const float* __restrict__ Wh, const float* __restrict__ a,
                     float* __restrict__ s1, float* __restrict__ s2) {
    int gw = (blockIdx.x * blockDim.x + threadIdx.x) >> 5;
    int lane = threadIdx.x & 31;
    if (gw >= 4 * NN) return;
    int h = gw >> 12;
    const float* row = Wh + (long)gw * 256;
    const float* ah = a + h * 512;
    float d1 = 0.f, d2 = 0.f;
    for (int f = lane; f < 256; f += 32) {
        float v = row[f];
        d1 += v * ah[f];
        d2 += v * ah[256 + f];
    }
    for (int o = 16; o; o >>= 1) {
        d1 += __shfl_xor_sync(0xFFFFFFFFu, d1, o);
        d2 += __shfl_xor_sync(0xFFFFFFFFu, d2, o);
    }
    if (lane == 0) { s1[gw] = d1; s2[gw] = d2; }
}

// per-head M = leaky(max s1 + max s2)
__global__ void k_max4(const float* __restrict__ s1, const float* __restrict__ s2,
                       float* __restrict__ Mp, int nheads) {
    int h = blockIdx.x;
    const float* a = s1 + (long)h * NN;
    const float* b = s2 + (long)h * NN;
    __shared__ float m1s[512], m2s[512];
    int t = threadIdx.x;
    float m1 = -1e30f, m2 = -1e30f;
    for (int i = t; i < NN; i += 512) { m1 = fmaxf(m1, a[i]); m2 = fmaxf(m2, b[i]); }
    m1s[t] = m1; m2s[t] = m2; __syncthreads();
    for (int s = 256; s; s >>= 1) {
        if (t < s) { m1s[t] = fmaxf(m1s[t], m1s[t + s]); m2s[t] = fmaxf(m2s[t], m2s[t + s]); }
        __syncthreads();
    }
    if (t == 0) Mp[h] = lrelu(m1s[0] + m2s[0]);
}

// ---------------- bf16 sparse aggregation (FOUT=256, 4 heads via blockIdx.y) ---
// out[i,:] = elu( (sum_j w_ij * Whb[j,:]) / Z_i ),  w_ij = exp(lrelu(s1_i+s2_j)-M)
__global__ void __launch_bounds__(256) k_aggb(
    const uint4* __restrict__ Whb,   // packed bf16, 32 uint4 per row, heads contiguous
    const float* __restrict__ s1, const float* __restrict__ s2,
    const float* __restrict__ Mp,
    const int* __restrict__ rp, const int* __restrict__ ci,
    float* __restrict__ outBase, long headStride, int ostride) {
    int row = blockIdx.x;
    int h = blockIdx.y;
    const uint4* W = Whb + (long)h * NN * 32;
    const float* s1h = s1 + (long)h * NN;
    const float* s2h = s2 + (long)h * NN;
    float* out = outBase + (long)h * headStride + (long)row * ostride;

    int tid = threadIdx.x;
    int tx = tid & 31;   // feature group: 8 bf16 per thread
    int ty = tid >> 5;   // 0..7, neighbor lane

    __shared__ float sw[256];
    __shared__ int   sj[256];
    __shared__ float sz[256];
    __shared__ float sacc[8 * 256];

    float s1i = s1h[row];
    float M = Mp[h];
    int rs = rp[row], re = rp[row + 1];

    float acc[8] = {0.f,0.f,0.f,0.f,0.f,0.f,0.f,0.f};
    float z = 0.f;

    for (int base = rs; base < re; base += 256) {
        int n = min(256, re - base);
        __syncthreads();
        for (int t = tid; t < n; t += 256) {
            int j = ci[base + t];
            sj[t] = j;
            float w = __expf(lrelu(s1i + s2h[j]) - M);
            sw[t] = w;
            z += w;
        }
        __syncthreads();
        for (int t = ty; t < n; t += 8) {
            float w = sw[t];
            uint4 v = W[(long)sj[t] * 32 + tx];
#define UNP(u, k0) \
            acc[k0]   = fmaf(w, __uint_as_float((u) << 16),        acc[k0]);   \
            acc[k0+1] = fmaf(w, __uint_as_float((u) & 0xFFFF0000u), acc[k0+1]);
            UNP(v.x, 0) UNP(v.y, 2) UNP(v.z, 4) UNP(v.w, 6)
#undef UNP
        }
    }
    __syncthreads();
#pragma unroll
    for (int k = 0; k < 8; k++) sacc[ty * 256 + tx * 8 + k] = acc[k];
    sz[tid] = z;
    __syncthreads();
    for (int s = 128; s; s >>= 1) { if (tid < s) sz[tid] += sz[tid + s]; __syncthreads(); }
    for (int s = 4; s; s >>= 1) {
        if (ty < s) {
#pragma unroll
            for (int k = 0; k < 8; k++)
                sacc[ty * 256 + tx * 8 + k] += sacc[(ty + s) * 256 + tx * 8 + k];
        }
        __syncthreads();
    }
    if (ty == 0) {
        float inv = 1.0f / sz[0];
#pragma unroll
        for (int k = 0; k < 8; k++) {
            float o = sacc[tx * 8 + k] * inv;
            o = o > 0.f ? o : expm1f(o);   // elu (concat=True layers)
            out[tx * 8 + k] = o;
        }
    }
}

// fp32 aggregation (FOUT=64, out layer 0, no elu)
__global__ void k_agg64(const float* __restrict__ Wh, const float* __restrict__ s1,
                        const float* __restrict__ s2, const float* __restrict__ Mp,
                        const int* __restrict__ rp, const int* __restrict__ ci,
                        float* __restrict__ out) {
    constexpr int TX = 16, TY = 16;
    int row = blockIdx.x;
    int tid = threadIdx.x;
    int tx = tid % TX, ty = tid / TX;
    __shared__ float sw[256];
    __shared__ int sj[256];
    __shared__ float4 sacc[256];
    __shared__ float sz[256];
    float s1i = s1[row];
    float M = Mp[0];
    int rs = rp[row], re = rp[row + 1];
    float4 acc = make_float4(0.f, 0.f, 0.f, 0.f);
    float z = 0.f;
    for (int base = rs; base < re; base += 256) {
        int n = min(256, re - base);
        __syncthreads();
        for (int t = tid; t < n; t += 256) {
            int j = ci[base + t];
            sj[t] = j;
            float w = __expf(lrelu(s1i + s2[j]) - M);
            sw[t] = w;
            z += w;
        }
        __syncthreads();
        for (int t = ty; t < n; t += TY) {
            float w = sw[t];
            float4 v = reinterpret_cast<const float4*>(Wh + (long)sj[t] * 64)[tx];
            acc.x += w * v.x; acc.y += w * v.y; acc.z += w * v.z; acc.w += w * v.w;
        }
    }
    sacc[tid] = acc; sz[tid] = z; __syncthreads();
    for (int s = 128; s; s >>= 1) { if (tid < s) sz[tid] += sz[tid + s]; __syncthreads(); }
    if (ty == 0) {
        float4 a = sacc[tx];
#pragma unroll
        for (int yy = 1; yy < TY; yy++) {
            float4 b = sacc[yy * TX + tx];
            a.x += b.x; a.y += b.y; a.z += b.z; a.w += b.w;
        }
        float inv = 1.0f / sz[0];
        *reinterpret_cast<float4*>(out + (long)row * 64 + tx * 4) =
            make_float4(a.x * inv, a.y * inv, a.z * inv, a.w * inv);
    }
}

// FOUT == 1 aggregation (final output attention layer)
__global__ void k_agg1(const float* __restrict__ whc, const float* __restrict__ s1,
                       const float* __restrict__ s2, const float* __restrict__ Mp,
                       const int* __restrict__ rp, const int* __restrict__ ci,
                       float* __restrict__ out) {
    int row = blockIdx.x, tid = threadIdx.x;
    __shared__ float sa[256], szz[256];
    float s1i = s1[row], M = Mp[0];
    int rs = rp[row], re = rp[row + 1];
    float acc = 0.f, z = 0.f;
    for (int e = rs + tid; e < re; e += 256) {
        int j = ci[e];
        float w = __expf(lrelu(s1i + s2[j]) - M);
        z += w;
        acc += w * whc[j];
    }
    sa[tid] = acc; szz[tid] = z; __syncthreads();
    for (int s = 128; s; s >>= 1) {
        if (tid < s) { sa[tid] += sa[tid + s]; szz[tid] += szz[tid + s]; }
        __syncthreads();
    }
    if (tid == 0) out[row] = sa[0] / szz[0];
}

__global__ void k_out1s(const float* __restrict__ h, const float* __restrict__ Wo1,
                        const float* __restrict__ ao1, float* __restrict__ whc,
                        float* __restrict__ s1, float* __restrict__ s2) {
    int gw = (blockIdx.x * blockDim.x + threadIdx.x) >> 5;
    int lane = threadIdx.x & 31;
    if (gw >= NN) return;
    float d = 0.f;
    for (int f = lane; f < 64; f += 32) d += h[(long)gw * 64 + f] * Wo1[f];
    for (int o = 16; o; o >>= 1) d += __shfl_xor_sync(0xFFFFFFFFu, d, o);
    if (lane == 0) { whc[gw] = d; s1[gw] = d * ao1[0]; s2[gw] = d * ao1[1]; }
}

// ---------------- dense SGEMM (row-major, batched), fp32 + optional bf16 out --
__global__ void __launch_bounds__(256) k_sgemm(
    const float* __restrict__ A, const float* __restrict__ B, float* __restrict__ C,
    unsigned int* __restrict__ Cb,
    int M, int N, int K, long sA, long sB, long sC, long sCb) {
    A += (long)blockIdx.z * sA;
    B += (long)blockIdx.z * sB;
    C += (long)blockIdx.z * sC;
    if (Cb) Cb += (long)blockIdx.z * sCb;
    __shared__ __align__(16) float As[8][128];
    __shared__ __align__(16) float Bs[8][128];
    int tid = threadIdx.x;
    int m0 = blockIdx.y * 128, n0 = blockIdx.x * 128;
    int arow = tid >> 1;
    int acol = (tid & 1) * 4;
    int brow = tid >> 5;
    int bcol = (tid & 31) * 4;
    int tx = tid & 15, ty = tid >> 4;
    float acc[8][8] = {};
    for (int kk = 0; kk < K; kk += 8) {
        float4 av = *reinterpret_cast<const float4*>(A + (long)(m0 + arow) * K + kk + acol);
        As[acol + 0][arow] = av.x;
        As[acol + 1][arow] = av.y;
        As[acol + 2][arow] = av.z;
        As[acol + 3][arow] = av.w;
        float4 bv = make_float4(0.f, 0.f, 0.f, 0.f);
        if (n0 + bcol < N)
            bv = *reinterpret_cast<const float4*>(B + (long)(kk + brow) * N + n0 + bcol);
        *reinterpret_cast<float4*>(&Bs[brow][bcol]) = bv;
        __syncthreads();
#pragma unroll
        for (int k = 0; k < 8; k++) {
            float4 a0 = *reinterpret_cast<const float4*>(&As[k][ty * 8]);
            float4 a1 = *reinterpret_cast<const float4*>(&As[k][ty * 8 + 4]);
            float4 b0 = *reinterpret_cast<const float4*>(&Bs[k][tx * 8]);
            float4 b1 = *reinterpret_cast<const float4*>(&Bs[k][tx * 8 + 4]);
            float am[8] = { a0.x, a0.y, a0.z, a0.w, a1.x, a1.y, a1.z, a1.w };
            float bn[8] = { b0.x, b0.y, b0.z, b0.w, b1.x, b1.y, b1.z, b1.w };
#pragma unroll
            for (int i = 0; i < 8; i++)
#pragma unroll
                for (int j = 0; j < 8; j++) acc[i][j] += am[i] * bn[j];
        }
        __syncthreads();
    }
#pragma unroll
    for (int i = 0; i < 8; i++) {
        int r = m0 + ty * 8 + i;
#pragma unroll
        for (int j = 0; j < 8; j += 4) {
            int c = n0 + tx * 8 + j;
            if (c < N) {
                *reinterpret_cast<float4*>(C + (long)r * N + c) =
                    make_float4(acc[i][j], acc[i][j + 1], acc[i][j + 2], acc[i][j + 3]);
                if (Cb) {
                    __nv_bfloat162 p0 = __float22bfloat162_rn(make_float2(acc[i][j], acc[i][j + 1]));
                    __nv_bfloat162 p1 = __float22bfloat162_rn(make_float2(acc[i][j + 2], acc[i][j + 3]));
                    uint2 w;
                    w.x = *reinterpret_cast<unsigned int*>(&p0);
                    w.y = *reinterpret_cast<unsigned int*>(&p1);
                    *reinterpret_cast<uint2*>(Cb + (long)r * (N >> 1) + (c >> 1)) = w;
                }
            }
        }
    }
}

// ---------------- final degree MLP ----------------
__global__ void k_mlp(const float* __restrict__ hout, const float* __restrict__ dv,
                      const float* __restrict__ dW, const float* __restrict__ dW0,
                      const float* __restrict__ dW1, const float* __restrict__ dW01,
                      const float* __restrict__ dW2, const float* __restrict__ dW02,
                      const float* __restrict__ dV, const float* __restrict__ dV0,
                      float* __restrict__ out) {
    int i = blockIdx.x * blockDim.x + threadIdx.x;
    if (i >= NN) return;
    float hv = hout[i];
    float x0 = hv > 0.f ? hv : expm1f(hv);
    float x1 = dv[i];
    float h0[10];
#pragma unroll
    for (int k = 0; k < 10; k++)
        h0[k] = lrelu(x0 * dW[k] + x1 * dW[10 + k] + dW0[k]);
    float h1[20];
#pragma unroll
    for (int k = 0; k < 20; k++) {
        float t = dW01[k];
#pragma unroll
        for (int j = 0; j < 10; j++) t += h0[j] * dW1[j * 20 + k];
        h1[k] = lrelu(t);
    }
    float h2[10];
#pragma unroll
    for (int k = 0; k < 10; k++) {
        float t = dW02[k];
#pragma unroll
        for (int j = 0; j < 20; j++) t += h1[j] * dW2[j * 10 + k];
        h2[k] = lrelu(t);
    }
    float o = dV0[0];
#pragma unroll
    for (int j = 0; j < 10; j++) o += h2[j] * dV[j];
    out[i] = lrelu(o);
}

// ---------------- launch ----------------
extern "C" void kernel_launch(void* const* d_in, const int* in_sizes, int n_in,
                              void* d_out, int out_size) {
    const float* x     = (const float*)d_in[0];
    const float* adj   = (const float*)d_in[1];
    const int*   obs   = (const int*)d_in[2];
    const float* s_mat = (const float*)d_in[3];
    const float* theta = (const float*)d_in[4];
    const float* Wh0   = (const float*)d_in[5];
    const float* ah0   = (const float*)d_in[6];
    const float* Wh1   = (const float*)d_in[7];
    const float* ah1   = (const float*)d_in[8];
    const float* Wo0   = (const float*)d_in[9];
    const float* ao0   = (const float*)d_in[10];
    const float* Wo1   = (const float*)d_in[11];
    const float* ao1   = (const float*)d_in[12];
    const float* dW    = (const float*)d_in[13];
    const float* dW0   = (const float*)d_in[14];
    const float* dW1   = (const float*)d_in[15];
    const float* dW01  = (const float*)d_in[16];
    const float* dW2   = (const float*)d_in[17];
    const float* dW02  = (const float*)d_in[18];
    const float* dV    = (const float*)d_in[19];
    const float* dV0   = (const float*)d_in[20];
    float* out = (float*)d_out;

    float* fa = nullptr;
    int*   ia = nullptr;
    cudaGetSymbolAddress((void**)&fa, g_farena);
    cudaGetSymbolAddress((void**)&ia, g_iarena);

    float* hin  = fa + OFF_HIN;
    float* Wh   = fa + OFF_WH;
    float* h1b  = fa + OFF_H1;
    float* hcat = fa + OFF_HCAT;
    float* oWh  = fa + OFF_OWH;
    float* ho0  = fa + OFF_HO0;
    float* whc  = fa + OFF_WHC;
    float* hout = fa + OFF_HOUT;
    float* s1   = fa + OFF_S1;
    float* s2   = fa + OFF_S2;
    float* Mp   = fa + OFF_M;
    float* dv   = fa + OFF_DV;
    unsigned int* Whb = (unsigned int*)(fa + OFF_WHB);
    int* cnt = ia + OFF_CNT;
    int* rp  = ia + OFF_RP;
    int* ci  = ia + OFF_CI;

    const long NM = (long)NN * 256;

    // CSR of adjacency (shared by all 10 layers)
    k_count<<<NN, 256>>>(adj, cnt);
    k_scan<<<1, 1024>>>(cnt, rp);
    k_fill<<<NN, 256>>>(adj, rp, ci);

    // degree vector from s_mat
    k_rowsum<<<NN, 256>>>(s_mat, dv);

    // h_in = x + seed * theta
    k_merge<<<(NN * 512) / 256, 256>>>(x, obs, theta, hin);

    // ---- head layer 0 (all 4 heads): Wh = h_in @ Wh0[h]  (+ bf16 copy) ----
    k_sgemm<<<dim3(2, 32, 4), 256>>>(hin, Wh0, Wh, Whb, NN, 256, 512,
                                     0L, 512L * 256, NM, (long)NN * 128);
    k_s4<<<2048, 256>>>(Wh, ah0, s1, s2);
    k_max4<<<4, 512>>>(s1, s2, Mp, 4);
    k_aggb<<<dim3(NN, 4), 256>>>((const uint4*)Whb, s1, s2, Mp, rp, ci,
                                 h1b, NM, 256);

    // ---- head layer 1: Wh = h1 @ Wh1[h]; output into hcat columns ----
    k_sgemm<<<dim3(2, 32, 4), 256>>>(h1b, Wh1, Wh, Whb, NN, 256, 256,
                                     NM, 256L * 256, NM, (long)NN * 128);
    k_s4<<<2048, 256>>>(Wh, ah1, s1, s2);
    k_max4<<<4, 512>>>(s1, s2, Mp, 4);
    k_aggb<<<dim3(NN, 4), 256>>>((const uint4*)Whb, s1, s2, Mp, rp, ci,
                                 hcat, 256L, 1024);

    // ---- output layer 0: [4096,1024] @ [1024,64], concat=False ----
    k_sgemm<<<dim3(1, 32, 1), 256>>>(hcat, Wo0, oWh, nullptr, NN, 64, 1024,
                                     0L, 0L, 0L, 0L);
    k_s<<<512, 256>>>(oWh, ao0, 64, s1, s2);
    k_max4<<<1, 512>>>(s1, s2, Mp, 1);
    k_agg64<<<NN, 256>>>(oWh, s1, s2, Mp, rp, ci, ho0);

    // ---- output layer 1: Fout = 1 ----
    k_out1s<<<512, 256>>>(ho0, Wo1, ao1, whc, s1, s2);
    k_max4<<<1, 512>>>(s1, s2, Mp, 1);
    k_agg1<<<NN, 256>>>(whc, s1, s2, Mp, rp, ci, hout);

    // ---- elu + degree MLP ----
    k_mlp<<<16, 256>>>(hout, dv, dW, dW0, dW1, dW01, dW2, dW02, dV, dV0, out);
}

// round 3
// speedup vs baseline: 1.5759x; 1.5278x over previous
#include <cuda_runtime.h>
#include <cuda_bf16.h>
#include <math.h>

#define NN 4096
#define ALPHA 0.2f

__device__ __forceinline__ float lrelu(float v){ return v >= 0.f ? v : ALPHA * v; }

// ---------------- scratch arenas (device globals; no allocation) -------------
// offsets in floats (all multiples of 16 -> 64B aligned)
#define OFF_WH    0L          // fp32 Wh: 4*4096*256
#define OFF_OWH   4194304L    // 4096*64
#define OFF_HO0   4456448L    // 4096*64
#define OFF_WHC   4718592L    // 4096
#define OFF_HOUT  4722688L    // 4096
#define OFF_S1    4726784L    // 4*4096
#define OFF_S2    4743168L    // 4*4096
#define OFF_M     4759552L    // 16
#define OFF_DV    4759568L    // 4096
#define OFF_WHB   4763664L    // bf16 4*4096*256 -> 2097152 floats
#define OFF_HINB  6860816L    // bf16 4096*512   -> 1048576 floats
#define OFF_H1B   7909392L    // bf16 4*4096*256 -> 2097152 floats
#define OFF_HCATB 10006544L   // bf16 4096*1024  -> 2097152 floats
#define OFF_W0B   12103696L   // bf16 4*512*256  -> 262144 floats
#define OFF_W1B   12365840L   // bf16 4*256*256  -> 131072 floats
#define OFF_WO0B  12496912L   // bf16 1024*64    -> 32768 floats
#define FARENA_SZ 12600000L

#define OFF_CNT   0
#define OFF_RP    4096
#define OFF_CI    8200
#define IARENA_SZ 2200000

__device__ float g_farena[FARENA_SZ];
__device__ int   g_iarena[IARENA_SZ];

// ---------------- CSR construction ----------------
__global__ void k_count(const float* __restrict__ adj, int* __restrict__ cnt) {
    int row = blockIdx.x, tid = threadIdx.x;
    const float4* p = reinterpret_cast<const float4*>(adj + (long)row * NN);
    int c = 0;
    for (int i = tid; i < NN / 4; i += 256) {
        float4 v = p[i];
        c += (v.x > 0.f) + (v.y > 0.f) + (v.z > 0.f) + (v.w > 0.f);
    }
    __shared__ int s[256];
    s[tid] = c; __syncthreads();
    for (int st = 128; st; st >>= 1) { if (tid < st) s[tid] += s[tid + st]; __syncthreads(); }
    if (tid == 0) cnt[row] = s[0];
}

__global__ void k_scan(const int* __restrict__ cnt, int* __restrict__ rp) {
    __shared__ int s[1024];
    int t = threadIdx.x;
    int v[4]; int loc = 0;
#pragma unroll
    for (int k = 0; k < 4; k++) { v[k] = cnt[t * 4 + k]; loc += v[k]; }
    s[t] = loc; __syncthreads();
    for (int off = 1; off < 1024; off <<= 1) {
        int add = (t >= off) ? s[t - off] : 0;
        __syncthreads();
        s[t] += add;
        __syncthreads();
    }
    int run = (t == 0) ? 0 : s[t - 1];
#pragma unroll
    for (int k = 0; k < 4; k++) { rp[t * 4 + k] = run; run += v[k]; }
    if (t == 1023) rp[NN] = run;
}

__global__ void k_fill(const float* __restrict__ adj, const int* __restrict__ rp,
                       int* __restrict__ ci) {
    int row = blockIdx.x, tid = threadIdx.x;
    const float4* p = reinterpret_cast<const float4*>(adj + (long)row * NN);
    float4 vv[4]; int c = 0;
#pragma unroll
    for (int k = 0; k < 4; k++) {
        vv[k] = p[tid + k * 256];
        c += (vv[k].x > 0.f) + (vv[k].y > 0.f) + (vv[k].z > 0.f) + (vv[k].w > 0.f);
    }
    __shared__ int s[256];
    s[tid] = c; __syncthreads();
    for (int off = 1; off < 256; off <<= 1) {
        int add = (tid >= off) ? s[tid - off] : 0;
        __syncthreads();
        s[tid] += add;
        __syncthreads();
    }
    int pos = rp[row] + ((tid == 0) ? 0 : s[tid - 1]);
#pragma unroll
    for (int k = 0; k < 4; k++) {
        int col = (tid + k * 256) * 4;
        if (vv[k].x > 0.f) ci[pos++] = col;
        if (vv[k].y > 0.f) ci[pos++] = col + 1;
        if (vv[k].z > 0.f) ci[pos++] = col + 2;
        if (vv[k].w > 0.f) ci[pos++] = col + 3;
    }
}

// ---------------- misc ----------------
__global__ void k_rowsum(const float* __restrict__ sm, float* __restrict__ dv) {
    int row = blockIdx.x, tid = threadIdx.x;
    const float4* p = reinterpret_cast<const float4*>(sm + (long)row * NN);
    float acc = 0.f;
    for (int i = tid; i < NN / 4; i += 256) { float4 v = p[i]; acc += v.x + v.y + v.z + v.w; }
    __shared__ float s[256];
    s[tid] = acc; __syncthreads();
    for (int st = 128; st; st >>= 1) { if (tid < st) s[tid] += s[tid + st]; __syncthreads(); }
    if (tid == 0) dv[row] = s[0];
}

// h_in bf16 = x + seed*theta  (vectorized over float4)
__global__ void k_mergeb(const float4* __restrict__ x, const int* __restrict__ obs,
                         const float4* __restrict__ theta, uint2* __restrict__ out) {
    long i = (long)blockIdx.x * blockDim.x + threadIdx.x;  // 4096*128 float4s
    int row = (int)(i >> 7);
    int f4 = (int)(i & 127);
    float4 v = x[i];
    if (obs[row] == 1) { float4 t = theta[f4]; v.x += t.x; v.y += t.y; v.z += t.z; v.w += t.w; }
    __nv_bfloat162 p0 = __float22bfloat162_rn(make_float2(v.x, v.y));
    __nv_bfloat162 p1 = __float22bfloat162_rn(make_float2(v.z, v.w));
    uint2 w;
    w.x = *reinterpret_cast<unsigned int*>(&p0);
    w.y = *reinterpret_cast<unsigned int*>(&p1);
    out[i] = w;
}

// generic fp32 -> bf16 conversion (n4 = count/4)
__global__ void k_cvt(const float4* __restrict__ in, uint2* __restrict__ out, int n4) {
    int i = blockIdx.x * blockDim.x + threadIdx.x;
    if (i >= n4) return;
    float4 v = in[i];
    __nv_bfloat162 p0 = __float22bfloat162_rn(make_float2(v.x, v.y));
    __nv_bfloat162 p1 = __float22bfloat162_rn(make_float2(v.z, v.w));
    uint2 w;
    w.x = *reinterpret_cast<unsigned int*>(&p0);
    w.y = *reinterpret_cast<unsigned int*>(&p1);
    out[i] = w;
}

// s for a single matrix (out layer 0, fout=64)
__global__ void k_s(const float* __restrict__ Wh, const float* __restrict__ a, int fout,
                    float* __restrict__ s1, float* __restrict__ s2) {
    int gw = (blockIdx.x * blockDim.x + threadIdx.x) >> 5;
    int lane = threadIdx.x & 31;
    if (gw >= NN) return;
    const float* row = Wh + (long)gw * fout;
    float d1 = 0.f, d2 = 0.f;
    for (int f = lane; f < fout; f += 32) {
        float v = row[f];
        d1 += v * a[f];
        d2 += v * a[fout + f];
    }
    for (int o = 16; o; o >>= 1) {
        d1 += __shfl_xor_sync(0xFFFFFFFFu, d1, o);
        d2 += __shfl_xor_sync(0xFFFFFFFFu, d2, o);
    }
    if (lane == 0) { s1[gw] = d1; s2[gw] = d2; }
}

// s for all 4 heads at once (fout=256, heads contiguous in Wh)
__global__ void k_s4(const float* __restrict__ Wh, const float* __restrict__ a,
                     float* __restrict__ s1, float* __restrict__ s2) {
    int gw = (blockIdx.x * blockDim.x + threadIdx.x) >> 5;
    int lane = threadIdx.x & 31;
    if (gw >= 4 * NN) return;
    int h = gw >> 12;
    const float* row = Wh + (long)gw * 256;
    const float* ah = a + h * 512;
    float d1 = 0.f, d2 = 0.f;
    for (int f = lane; f < 256; f += 32) {
        float v = row[f];
        d1 += v * ah[f];
        d2 += v * ah[256 + f];
    }
    for (int o = 16; o; o >>= 1) {
        d1 += __shfl_xor_sync(0xFFFFFFFFu, d1, o);
        d2 += __shfl_xor_sync(0xFFFFFFFFu, d2, o);
    }
    if (lane == 0) { s1[gw] = d1; s2[gw] = d2; }
}

// per-head M = leaky(max s1 + max s2)
__global__ void k_max4(const float* __restrict__ s1, const float* __restrict__ s2,
                       float* __restrict__ Mp, int nheads) {
    int h = blockIdx.x;
    const float* a = s1 + (long)h * NN;
    const float* b = s2 + (long)h * NN;
    __shared__ float m1s[512], m2s[512];
    int t = threadIdx.x;
    float m1 = -1e30f, m2 = -1e30f;
    for (int i = t; i < NN; i += 512) { m1 = fmaxf(m1, a[i]); m2 = fmaxf(m2, b[i]); }
    m1s[t] = m1; m2s[t] = m2; __syncthreads();
    for (int s = 256; s; s >>= 1) {
        if (t < s) { m1s[t] = fmaxf(m1s[t], m1s[t + s]); m2s[t] = fmaxf(m2s[t], m2s[t + s]); }
        __syncthreads();
    }
    if (t == 0) Mp[h] = lrelu(m1s[0] + m2s[0]);
}

// ---------------- bf16 sparse aggregation (FOUT=256, 4 heads), bf16 output ----
__global__ void __launch_bounds__(256) k_aggb(
    const uint4* __restrict__ Whb,   // packed bf16, 32 uint4 per row, heads contiguous
    const float* __restrict__ s1, const float* __restrict__ s2,
    const float* __restrict__ Mp,
    const int* __restrict__ rp, const int* __restrict__ ci,
    __nv_bfloat16* __restrict__ outBase, long headStride, int ostride) {
    int row = blockIdx.x;
    int h = blockIdx.y;
    const uint4* W = Whb + (long)h * NN * 32;
    const float* s1h = s1 + (long)h * NN;
    const float* s2h = s2 + (long)h * NN;
    __nv_bfloat16* out = outBase + (long)h * headStride + (long)row * ostride;

    int tid = threadIdx.x;
    int tx = tid & 31;   // feature group: 8 bf16 per thread
    int ty = tid >> 5;   // 0..7, neighbor lane

    __shared__ float sw[256];
    __shared__ int   sj[256];
    __shared__ float sz[256];
    __shared__ float sacc[8 * 256];

    float s1i = s1h[row];
    float M = Mp[h];
    int rs = rp[row], re = rp[row + 1];

    float acc[8] = {0.f,0.f,0.f,0.f,0.f,0.f,0.f,0.f};
    float z = 0.f;

    for (int base = rs; base < re; base += 256) {
        int n = min(256, re - base);
        __syncthreads();
        for (int t = tid; t < n; t += 256) {
            int j = ci[base + t];
            sj[t] = j;
            float w = __expf(lrelu(s1i + s2h[j]) - M);
            sw[t] = w;
            z += w;
        }
        __syncthreads();
        for (int t = ty; t < n; t += 8) {
            float w = sw[t];
            uint4 v = W[(long)sj[t] * 32 + tx];
#define UNP(u, k0) \
            acc[k0]   = fmaf(w, __uint_as_float((u) << 16),        acc[k0]);   \
            acc[k0+1] = fmaf(w, __uint_as_float((u) & 0xFFFF0000u), acc[k0+1]);
            UNP(v.x, 0) UNP(v.y, 2) UNP(v.z, 4) UNP(v.w, 6)
#undef UNP
        }
    }
    __syncthreads();
#pragma unroll
    for (int k = 0; k < 8; k++) sacc[ty * 256 + tx * 8 + k] = acc[k];
    sz[tid] = z;
    __syncthreads();
    for (int s = 128; s; s >>= 1) { if (tid < s) sz[tid] += sz[tid + s]; __syncthreads(); }
    for (int s = 4; s; s >>= 1) {
        if (ty < s) {
#pragma unroll
            for (int k = 0; k < 8; k++)
                sacc[ty * 256 + tx * 8 + k] += sacc[(ty + s) * 256 + tx * 8 + k];
        }
        __syncthreads();
    }
    if (ty == 0) {
        float inv = 1.0f / sz[0];
        float o[8];
#pragma unroll
        for (int k = 0; k < 8; k++) {
            float t = sacc[tx * 8 + k] * inv;
            o[k] = t > 0.f ? t : expm1f(t);   // elu (concat=True layers)
        }
        uint4 w;
        __nv_bfloat162 p;
        p = __float22bfloat162_rn(make_float2(o[0], o[1])); w.x = *(unsigned int*)&p;
        p = __float22bfloat162_rn(make_float2(o[2], o[3])); w.y = *(unsigned int*)&p;
        p = __float22bfloat162_rn(make_float2(o[4], o[5])); w.z = *(unsigned int*)&p;
        p = __float22bfloat162_rn(make_float2(o[6], o[7])); w.w = *(unsigned int*)&p;
        *reinterpret_cast<uint4*>(out + tx * 8) = w;
    }
}

// fp32 aggregation (FOUT=64, out layer 0, no elu)
__global__ void k_agg64(const float* __restrict__ Wh, const float* __restrict__ s1,
                        const float* __restrict__ s2, const float* __restrict__ Mp,
                        const int* __restrict__ rp, const int* __restrict__ ci,
                        float* __restrict__ out) {
    constexpr int TX = 16, TY = 16;
    int row = blockIdx.x;
    int tid = threadIdx.x;
    int tx = tid % TX, ty = tid / TX;
    __shared__ float sw[256];
    __shared__ int sj[256];
    __shared__ float4 sacc[256];
    __shared__ float sz[256];
    float s1i = s1[row];
    float M = Mp[0];
    int rs = rp[row], re = rp[row + 1];
    float4 acc = make_float4(0.f, 0.f, 0.f, 0.f);
    float z = 0.f;
    for (int base = rs; base < re; base += 256) {
        int n = min(256, re - base);
        __syncthreads();
        for (int t = tid; t < n; t += 256) {
            int j = ci[base + t];
            sj[t] = j;
            float w = __expf(lrelu(s1i + s2[j]) - M);
            sw[t] = w;
            z += w;
        }
        __syncthreads();
        for (int t = ty; t < n; t += TY) {
            float w = sw[t];
            float4 v = reinterpret_cast<const float4*>(Wh + (long)sj[t] * 64)[tx];
            acc.x += w * v.x; acc.y += w * v.y; acc.z += w * v.z; acc.w += w * v.w;
        }
    }
    sacc[tid] = acc; sz[tid] = z; __syncthreads();
    for (int s = 128; s; s >>= 1) { if (tid < s) sz[tid] += sz[tid + s]; __syncthreads(); }
    if (ty == 0) {
        float4 a = sacc[tx];
#pragma unroll
        for (int yy = 1; yy < TY; yy++) {
            float4 b = sacc[yy * TX + tx];
            a.x += b.x; a.y += b.y; a.z += b.z; a.w += b.w;
        }
        float inv = 1.0f / sz[0];
        *reinterpret_cast<float4*>(out + (long)row * 64 + tx * 4) =
            make_float4(a.x * inv, a.y * inv, a.z * inv, a.w * inv);
    }
}

// FOUT == 1 aggregation (final output attention layer)
__global__ void k_agg1(const float* __restrict__ whc, const float* __restrict__ s1,
                       const float* __restrict__ s2, const float* __restrict__ Mp,
                       const int* __restrict__ rp, const int* __restrict__ ci,
                       float* __restrict__ out) {
    int row = blockIdx.x, tid = threadIdx.x;
    __shared__ float sa[256], szz[256];
    float s1i = s1[row], M = Mp[0];
    int rs = rp[row], re = rp[row + 1];
    float acc = 0.f, z = 0.f;
    for (int e = rs + tid; e < re; e += 256) {
        int j = ci[e];
        float w = __expf(lrelu(s1i + s2[j]) - M);
        z += w;
        acc += w * whc[j];
    }
    sa[tid] = acc; szz[tid] = z; __syncthreads();
    for (int s = 128; s; s >>= 1) {
        if (tid < s) { sa[tid] += sa[tid + s]; szz[tid] += szz[tid + s]; }
        __syncthreads();
    }
    if (tid == 0) out[row] = sa[0] / szz[0];
}

__global__ void k_out1s(const float* __restrict__ h, const float* __restrict__ Wo1,
                        const float* __restrict__ ao1, float* __restrict__ whc,
                        float* __restrict__ s1, float* __restrict__ s2) {
    int gw = (blockIdx.x * blockDim.x + threadIdx.x) >> 5;
    int lane = threadIdx.x & 31;
    if (gw >= NN) return;
    float d = 0.f;
    for (int f = lane; f < 64; f += 32) d += h[(long)gw * 64 + f] * Wo1[f];
    for (int o = 16; o; o >>= 1) d += __shfl_xor_sync(0xFFFFFFFFu, d, o);
    if (lane == 0) { whc[gw] = d; s1[gw] = d * ao1[0]; s2[gw] = d * ao1[1]; }
}

// ---------------- bf16 tensor-core GEMM: C = A @ B ----------------
// BM=128 BN=128 BK=32, 256 threads = 8 warps (4 M-warps x 2 N-warps),
// warp tile 32x64 = 2 x 8 m16n8k16 mma. fp32 accumulate.
// A row-major [M,K] bf16, B row-major [K,N] bf16.
// Writes C fp32 and optional Cb (packed bf16 pairs as uint).
__device__ __forceinline__ void ldsm4(unsigned& r0, unsigned& r1, unsigned& r2, unsigned& r3,
                                      unsigned addr) {
    asm volatile("ldmatrix.sync.aligned.m8n8.x4.shared.b16 {%0,%1,%2,%3}, [%4];"
                 : "=r"(r0), "=r"(r1), "=r"(r2), "=r"(r3) : "r"(addr));
}
__device__ __forceinline__ void ldsm4t(unsigned& r0, unsigned& r1, unsigned& r2, unsigned& r3,
                                       unsigned addr) {
    asm volatile("ldmatrix.sync.aligned.m8n8.x4.trans.shared.b16 {%0,%1,%2,%3}, [%4];"
                 : "=r"(r0), "=r"(r1), "=r"(r2), "=r"(r3) : "r"(addr));
}
__device__ __forceinline__ void mma16816(float* c, unsigned a0, unsigned a1, unsigned a2,
                                         unsigned a3, unsigned b0, unsigned b1) {
    asm volatile(
        "mma.sync.aligned.m16n8k16.row.col.f32.bf16.bf16.f32 "
        "{%0,%1,%2,%3},{%4,%5,%6,%7},{%8,%9},{%0,%1,%2,%3};"
        : "+f"(c[0]), "+f"(c[1]), "+f"(c[2]), "+f"(c[3])
        : "r"(a0), "r"(a1), "r"(a2), "r"(a3), "r"(b0), "r"(b1));
}

#define GA_ROWB 80    // A smem row stride bytes (64B data + 16B pad: conflict-free ldmatrix)
#define GB_ROWB 272   // B smem row stride bytes (256B data + 16B pad)
#define GA_BYTES (128 * GA_ROWB)

__global__ void __launch_bounds__(256, 2) k_bgemm(
    const __nv_bfloat16* __restrict__ A, const __nv_bfloat16* __restrict__ B,
    float* __restrict__ C, unsigned int* __restrict__ Cb,
    int M, int N, int K, long sA, long sB, long sC, long sCb) {
    __shared__ __align__(16) unsigned char sm[GA_BYTES + 32 * GB_ROWB];
    A += (long)blockIdx.z * sA;
    B += (long)blockIdx.z * sB;
    C += (long)blockIdx.z * sC;
    if (Cb) Cb += (long)blockIdx.z * sCb;

    int tid = threadIdx.x;
    int warp = tid >> 5, lane = tid & 31;
    int wm = warp & 3, wn = warp >> 2;
    int m0 = blockIdx.y * 128, n0 = blockIdx.x * 128;

    uint4* As4 = reinterpret_cast<uint4*>(sm);
    uint4* Bs4 = reinterpret_cast<uint4*>(sm + GA_BYTES);

    int ar = tid >> 2;           // 0..63
    int ac = tid & 3;            // 16B chunk (8 bf16)
    int br = tid >> 4;           // 0..15
    int bc = tid & 15;
    bool bok = (n0 + bc * 8) < N;

    unsigned sA_base = (unsigned)__cvta_generic_to_shared(sm);
    unsigned sB_base = sA_base + GA_BYTES;
    int sub = lane >> 3, r = lane & 7;

    float acc[2][8][4] = {};
    int KT = K / 32;
    uint4 av0, av1, bv0, bv1;
    const uint4 zero4 = make_uint4(0, 0, 0, 0);

    // prefetch iter 0
    av0 = reinterpret_cast<const uint4*>(A + (long)(m0 + ar) * K)[ac];
    av1 = reinterpret_cast<const uint4*>(A + (long)(m0 + ar + 64) * K)[ac];
    bv0 = bok ? *reinterpret_cast<const uint4*>(B + (long)br * N + n0 + bc * 8) : zero4;
    bv1 = bok ? *reinterpret_cast<const uint4*>(B + (long)(br + 16) * N + n0 + bc * 8) : zero4;

    for (int it = 0; it < KT; it++) {
        As4[ar * 5 + ac] = av0;
        As4[(ar + 64) * 5 + ac] = av1;
        Bs4[br * 17 + bc] = bv0;
        Bs4[(br + 16) * 17 + bc] = bv1;
        __syncthreads();

        if (it + 1 < KT) {
            int kof = (it + 1) * 32;
            av0 = reinterpret_cast<const uint4*>(A + (long)(m0 + ar) * K + kof)[ac];
            av1 = reinterpret_cast<const uint4*>(A + (long)(m0 + ar + 64) * K + kof)[ac];
            bv0 = bok ? *reinterpret_cast<const uint4*>(B + (long)(kof + br) * N + n0 + bc * 8) : zero4;
            bv1 = bok ? *reinterpret_cast<const uint4*>(B + (long)(kof + br + 16) * N + n0 + bc * 8) : zero4;
        }

#pragma unroll
        for (int ks = 0; ks < 2; ks++) {
            unsigned a[2][4];
#pragma unroll
            for (int i = 0; i < 2; i++) {
                unsigned addr = sA_base
                    + (unsigned)((wm * 32 + i * 16 + (sub & 1) * 8 + r) * GA_ROWB
                                 + ks * 32 + (sub >> 1) * 16);
                ldsm4(a[i][0], a[i][1], a[i][2], a[i][3], addr);
            }
            unsigned b[4][4];
#pragma unroll
            for (int j = 0; j < 4; j++) {
                unsigned addr = sB_base
                    + (unsigned)((ks * 16 + (sub & 1) * 8 + r) * GB_ROWB
                                 + (wn * 64 + j * 16 + (sub >> 1) * 8) * 2);
                ldsm4t(b[j][0], b[j][1], b[j][2], b[j][3], addr);
            }
#pragma unroll
            for (int i = 0; i < 2; i++) {
#pragma unroll
                for (int j = 0; j < 4; j++) {
                    mma16816(acc[i][2 * j],     a[i][0], a[i][1], a[i][2], a[i][3],
                             b[j][0], b[j][1]);
                    mma16816(acc[i][2 * j + 1], a[i][0], a[i][1], a[i][2], a[i][3],
                             b[j][2], b[j][3]);
                }
            }
        }
        __syncthreads();
    }

    // epilogue
    int g = lane >> 2, ti = lane & 3;
#pragma unroll
    for (int i = 0; i < 2; i++) {
#pragma unroll
        for (int jj = 0; jj < 8; jj++) {
            int row = m0 + wm * 32 + i * 16 + g;
            int col = n0 + wn * 64 + jj * 8 + ti * 2;
            if (col < N) {
                float* c = acc[i][jj];
                *reinterpret_cast<float2*>(C + (long)row * N + col) = make_float2(c[0], c[1]);
                *reinterpret_cast<float2*>(C + (long)(row + 8) * N + col) = make_float2(c[2], c[3]);
                if (Cb) {
                    __nv_bfloat162 p0 = __float22bfloat162_rn(make_float2(c[0], c[1]));
                    __nv_bfloat162 p1 = __float22bfloat162_rn(make_float2(c[2], c[3]));
                    Cb[((long)row * N + col) >> 1] = *reinterpret_cast<unsigned int*>(&p0);
                    Cb[((long)(row + 8) * N + col) >> 1] = *reinterpret_cast<unsigned int*>(&p1);
                }
            }
        }
    }
}

// ---------------- final degree MLP ----------------
__global__ void k_mlp(const float* __restrict__ hout, const float* __restrict__ dv,
                      const float* __restrict__ dW, const float* __restrict__ dW0,
                      const float* __restrict__ dW1, const float* __restrict__ dW01,
                      const float* __restrict__ dW2, const float* __restrict__ dW02,
                      const float* __restrict__ dV, const float* __restrict__ dV0,
                      float* __restrict__ out) {
    int i = blockIdx.x * blockDim.x + threadIdx.x;
    if (i >= NN) return;
    float hv = hout[i];
    float x0 = hv > 0.f ? hv : expm1f(hv);
    float x1 = dv[i];
    float h0[10];
#pragma unroll
    for (int k = 0; k < 10; k++)
        h0[k] = lrelu(x0 * dW[k] + x1 * dW[10 + k] + dW0[k]);
    float h1[20];
#pragma unroll
    for (int k = 0; k < 20; k++) {
        float t = dW01[k];
#pragma unroll
        for (int j = 0; j < 10; j++) t += h0[j] * dW1[j * 20 + k];
        h1[k] = lrelu(t);
    }
    float h2[10];
#pragma unroll
    for (int k = 0; k < 10; k++) {
        float t = dW02[k];
#pragma unroll
        for (int j = 0; j < 20; j++) t += h1[j] * dW2[j * 10 + k];
        h2[k] = lrelu(t);
    }
    float o = dV0[0];
#pragma unroll
    for (int j = 0; j < 10; j++) o += h2[j] * dV[j];
    out[i] = lrelu(o);
}

// ---------------- launch ----------------
extern "C" void kernel_launch(void* const* d_in, const int* in_sizes, int n_in,
                              void* d_out, int out_size) {
    const float* x     = (const float*)d_in[0];
    const float* adj   = (const float*)d_in[1];
    const int*   obs   = (const int*)d_in[2];
    const float* s_mat = (const float*)d_in[3];
    const float* theta = (const float*)d_in[4];
    const float* Wh0   = (const float*)d_in[5];
    const float* ah0   = (const float*)d_in[6];
    const float* Wh1   = (const float*)d_in[7];
    const float* ah1   = (const float*)d_in[8];
    const float* Wo0   = (const float*)d_in[9];
    const float* ao0   = (const float*)d_in[10];
    const float* Wo1   = (const float*)d_in[11];
    const float* ao1   = (const float*)d_in[12];
    const float* dW    = (const float*)d_in[13];
    const float* dW0   = (const float*)d_in[14];
    const float* dW1   = (const float*)d_in[15];
    const float* dW01  = (const float*)d_in[16];
    const float* dW2   = (const float*)d_in[17];
    const float* dW02  = (const float*)d_in[18];
    const float* dV    = (const float*)d_in[19];
    const float* dV0   = (const float*)d_in[20];
    float* out = (float*)d_out;

    float* fa = nullptr;
    int*   ia = nullptr;
    cudaGetSymbolAddress((void**)&fa, g_farena);
    cudaGetSymbolAddress((void**)&ia, g_iarena);

    float* Wh   = fa + OFF_WH;
    float* oWh  = fa + OFF_OWH;
    float* ho0  = fa + OFF_HO0;
    float* whc  = fa + OFF_WHC;
    float* hout = fa + OFF_HOUT;
    float* s1   = fa + OFF_S1;
    float* s2   = fa + OFF_S2;
    float* Mp   = fa + OFF_M;
    float* dv   = fa + OFF_DV;
    __nv_bfloat16* Whb   = (__nv_bfloat16*)(fa + OFF_WHB);
    __nv_bfloat16* hinb  = (__nv_bfloat16*)(fa + OFF_HINB);
    __nv_bfloat16* h1bb  = (__nv_bfloat16*)(fa + OFF_H1B);
    __nv_bfloat16* hcatb = (__nv_bfloat16*)(fa + OFF_HCATB);
    __nv_bfloat16* W0b   = (__nv_bfloat16*)(fa + OFF_W0B);
    __nv_bfloat16* W1b   = (__nv_bfloat16*)(fa + OFF_W1B);
    __nv_bfloat16* Wo0b  = (__nv_bfloat16*)(fa + OFF_WO0B);
    int* cnt = ia + OFF_CNT;
    int* rp  = ia + OFF_RP;
    int* ci  = ia + OFF_CI;

    const long NM = (long)NN * 256;

    // CSR of adjacency (shared by all 10 layers)
    k_count<<<NN, 256>>>(adj, cnt);
    k_scan<<<1, 1024>>>(cnt, rp);
    k_fill<<<NN, 256>>>(adj, rp, ci);

    // degree vector from s_mat
    k_rowsum<<<NN, 256>>>(s_mat, dv);

    // bf16 conversions (weights) + merged input
    k_mergeb<<<2048, 256>>>((const float4*)x, obs, (const float4*)theta, (uint2*)hinb);
    k_cvt<<<512, 256>>>((const float4*)Wh0, (uint2*)W0b, 131072);   // 4*512*256
    k_cvt<<<256, 256>>>((const float4*)Wh1, (uint2*)W1b, 65536);    // 4*256*256
    k_cvt<<<64, 256>>>((const float4*)Wo0, (uint2*)Wo0b, 16384);    // 1024*64

    // ---- head layer 0 (all 4 heads): Wh = h_in @ Wh0[h] (fp32 + bf16 copies) ----
    k_bgemm<<<dim3(2, 32, 4), 256>>>(hinb, W0b, Wh, (unsigned int*)Whb,
                                     NN, 256, 512, 0L, 512L * 256, NM, (long)NN * 128);
    k_s4<<<2048, 256>>>(Wh, ah0, s1, s2);
    k_max4<<<4, 512>>>(s1, s2, Mp, 4);
    k_aggb<<<dim3(NN, 4), 256>>>((const uint4*)Whb, s1, s2, Mp, rp, ci,
                                 h1bb, NM, 256);

    // ---- head layer 1: Wh = h1 @ Wh1[h]; agg output into hcat columns ----
    k_bgemm<<<dim3(2, 32, 4), 256>>>(h1bb, W1b, Wh, (unsigned int*)Whb,
                                     NN, 256, 256, NM, 256L * 256, NM, (long)NN * 128);
    k_s4<<<2048, 256>>>(Wh, ah1, s1, s2);
    k_max4<<<4, 512>>>(s1, s2, Mp, 4);
    k_aggb<<<dim3(NN, 4), 256>>>((const uint4*)Whb, s1, s2, Mp, rp, ci,
                                 hcatb, 256L, 1024);

    // ---- output layer 0: [4096,1024] @ [1024,64], concat=False ----
    k_bgemm<<<dim3(1, 32, 1), 256>>>(hcatb, Wo0b, oWh, nullptr,
                                     NN, 64, 1024, 0L, 0L, 0L, 0L);
    k_s<<<512, 256>>>(oWh, ao0, 64, s1, s2);
    k_max4<<<1, 512>>>(s1, s2, Mp, 1);
    k_agg64<<<NN, 256>>>(oWh, s1, s2, Mp, rp, ci, ho0);

    // ---- output layer 1: Fout = 1 ----
    k_out1s<<<512, 256>>>(ho0, Wo1, ao1, whc, s1, s2);
    k_max4<<<1, 512>>>(s1, s2, Mp, 1);
    k_agg1<<<NN, 256>>>(whc, s1, s2, Mp, rp, ci, hout);

    // ---- elu + degree MLP ----
    k_mlp<<<16, 256>>>(hout, dv, dW, dW0, dW1, dW01, dW2, dW02, dV, dV0, out);
}

// round 4
// speedup vs baseline: 1.9638x; 1.2461x over previous
#include <cuda_runtime.h>
#include <cuda_bf16.h>
#include <math.h>

#define NN 4096
#define ALPHA 0.2f

__device__ __forceinline__ float lrelu(float v){ return v >= 0.f ? v : ALPHA * v; }

// ---------------- scratch arenas (device globals; no allocation) -------------
#define OFF_P0    0L          // fp32 P0: 8*512 = 4096
#define OFF_P1    4096L       // fp32 P1: 8*256 = 2048
#define OFF_OWH   8192L       // 4096*64
#define OFF_HO0   270336L     // 4096*64
#define OFF_WHC   532480L     // 4096
#define OFF_HOUT  536576L     // 4096
#define OFF_S1    540672L     // 4*4096
#define OFF_S2    557056L     // 4*4096
#define OFF_M     573440L     // 16
#define OFF_DV    573456L     // 4096
#define OFF_WHB   577552L     // bf16 4*4096*256 -> 2097152 floats
#define OFF_HINB  2674704L    // bf16 4096*512   -> 1048576 floats
#define OFF_H1B   3723280L    // bf16 4*4096*256 -> 2097152 floats
#define OFF_HCATB 5820432L    // bf16 4096*1024  -> 2097152 floats
#define OFF_W0B   7917584L    // bf16 4*512*256  -> 262144 floats
#define OFF_W1B   8179728L    // bf16 4*256*256  -> 131072 floats
#define OFF_WO0B  8310800L    // bf16 1024*64    -> 32768 floats
#define FARENA_SZ 8400000L

#define OFF_CNT   0
#define OFF_RP    4096
#define OFF_CI    8200
#define IARENA_SZ 2200000

__device__ float g_farena[FARENA_SZ];
__device__ int   g_iarena[IARENA_SZ];

// ---------------- CSR construction ----------------
__global__ void k_count(const float* __restrict__ adj, int* __restrict__ cnt) {
    int row = blockIdx.x, tid = threadIdx.x;
    const float4* p = reinterpret_cast<const float4*>(adj + (long)row * NN);
    int c = 0;
    for (int i = tid; i < NN / 4; i += 256) {
        float4 v = p[i];
        c += (v.x > 0.f) + (v.y > 0.f) + (v.z > 0.f) + (v.w > 0.f);
    }
    __shared__ int s[256];
    s[tid] = c; __syncthreads();
    for (int st = 128; st; st >>= 1) { if (tid < st) s[tid] += s[tid + st]; __syncthreads(); }
    if (tid == 0) cnt[row] = s[0];
}

__global__ void k_scan(const int* __restrict__ cnt, int* __restrict__ rp) {
    __shared__ int s[1024];
    int t = threadIdx.x;
    int v[4]; int loc = 0;
#pragma unroll
    for (int k = 0; k < 4; k++) { v[k] = cnt[t * 4 + k]; loc += v[k]; }
    s[t] = loc; __syncthreads();
    for (int off = 1; off < 1024; off <<= 1) {
        int add = (t >= off) ? s[t - off] : 0;
        __syncthreads();
        s[t] += add;
        __syncthreads();
    }
    int run = (t == 0) ? 0 : s[t - 1];
#pragma unroll
    for (int k = 0; k < 4; k++) { rp[t * 4 + k] = run; run += v[k]; }
    if (t == 1023) rp[NN] = run;
}

__global__ void k_fill(const float* __restrict__ adj, const int* __restrict__ rp,
                       int* __restrict__ ci) {
    int row = blockIdx.x, tid = threadIdx.x;
    const float4* p = reinterpret_cast<const float4*>(adj + (long)row * NN);
    float4 vv[4]; int c = 0;
#pragma unroll
    for (int k = 0; k < 4; k++) {
        vv[k] = p[tid + k * 256];
        c += (vv[k].x > 0.f) + (vv[k].y > 0.f) + (vv[k].z > 0.f) + (vv[k].w > 0.f);
    }
    __shared__ int s[256];
    s[tid] = c; __syncthreads();
    for (int off = 1; off < 256; off <<= 1) {
        int add = (tid >= off) ? s[tid - off] : 0;
        __syncthreads();
        s[tid] += add;
        __syncthreads();
    }
    int pos = rp[row] + ((tid == 0) ? 0 : s[tid - 1]);
#pragma unroll
    for (int k = 0; k < 4; k++) {
        int col = (tid + k * 256) * 4;
        if (vv[k].x > 0.f) ci[pos++] = col;
        if (vv[k].y > 0.f) ci[pos++] = col + 1;
        if (vv[k].z > 0.f) ci[pos++] = col + 2;
        if (vv[k].w > 0.f) ci[pos++] = col + 3;
    }
}

// ---------------- misc ----------------
__global__ void k_rowsum(const float* __restrict__ sm, float* __restrict__ dv) {
    int row = blockIdx.x, tid = threadIdx.x;
    const float4* p = reinterpret_cast<const float4*>(sm + (long)row * NN);
    float acc = 0.f;
    for (int i = tid; i < NN / 4; i += 256) { float4 v = p[i]; acc += v.x + v.y + v.z + v.w; }
    __shared__ float s[256];
    s[tid] = acc; __syncthreads();
    for (int st = 128; st; st >>= 1) { if (tid < st) s[tid] += s[tid + st]; __syncthreads(); }
    if (tid == 0) dv[row] = s[0];
}

__global__ void k_mergeb(const float4* __restrict__ x, const int* __restrict__ obs,
                         const float4* __restrict__ theta, uint2* __restrict__ out) {
    long i = (long)blockIdx.x * blockDim.x + threadIdx.x;
    int row = (int)(i >> 7);
    int f4 = (int)(i & 127);
    float4 v = x[i];
    if (obs[row] == 1) { float4 t = theta[f4]; v.x += t.x; v.y += t.y; v.z += t.z; v.w += t.w; }
    __nv_bfloat162 p0 = __float22bfloat162_rn(make_float2(v.x, v.y));
    __nv_bfloat162 p1 = __float22bfloat162_rn(make_float2(v.z, v.w));
    uint2 w;
    w.x = *reinterpret_cast<unsigned int*>(&p0);
    w.y = *reinterpret_cast<unsigned int*>(&p1);
    out[i] = w;
}

__global__ void k_cvt(const float4* __restrict__ in, uint2* __restrict__ out, int n4) {
    int i = blockIdx.x * blockDim.x + threadIdx.x;
    if (i >= n4) return;
    float4 v = in[i];
    __nv_bfloat162 p0 = __float22bfloat162_rn(make_float2(v.x, v.y));
    __nv_bfloat162 p1 = __float22bfloat162_rn(make_float2(v.z, v.w));
    uint2 w;
    w.x = *reinterpret_cast<unsigned int*>(&p0);
    w.y = *reinterpret_cast<unsigned int*>(&p1);
    out[i] = w;
}

// P[(2h+c)*Fin + f] = sum_d W[h,f,d] * a[h, c*256 + d]   (W: [4][Fin][256], a: [4][512])
__global__ void k_wa(const float* __restrict__ W, const float* __restrict__ a,
                     float* __restrict__ P, int Fin) {
    int h = blockIdx.y;
    int idx = blockIdx.x * 8 + (threadIdx.x >> 5);
    int lane = threadIdx.x & 31;
    if (idx >= 2 * Fin) return;
    int c = idx / Fin, f = idx % Fin;
    const float* wrow = W + ((long)h * Fin + f) * 256;
    const float* av = a + h * 512 + c * 256;
    float d = 0.f;
    for (int k = lane; k < 256; k += 32) d = fmaf(wrow[k], av[k], d);
    for (int o = 16; o; o >>= 1) d += __shfl_xor_sync(0xFFFFFFFFu, d, o);
    if (lane == 0) P[(2 * h + c) * Fin + f] = d;
}

// s1/s2 from bf16 activations: s1[h*NN+row] = dot(act_h[row,:], P[2h]), s2 with P[2h+1]
__global__ void __launch_bounds__(256) k_sb(
    const __nv_bfloat16* __restrict__ act, long headStride,
    const float* __restrict__ P, int K,
    float* __restrict__ s1, float* __restrict__ s2) {
    __shared__ float Ps[4096];
    int tid = threadIdx.x;
    for (int i = tid; i < 8 * K; i += 256) Ps[i] = P[i];
    __syncthreads();
    int gw = blockIdx.x * 8 + (tid >> 5);
    int lane = tid & 31;
    int row = gw >> 2, h = gw & 3;
    const __nv_bfloat16* a = act + (long)h * headStride + (long)row * K;
    const float* p1 = Ps + (2 * h) * K;
    const float* p2 = p1 + K;
    float d1 = 0.f, d2 = 0.f;
    for (int f = lane * 2; f < K; f += 64) {
        unsigned u = *reinterpret_cast<const unsigned*>(a + f);
        float x0 = __uint_as_float(u << 16);
        float x1 = __uint_as_float(u & 0xFFFF0000u);
        d1 = fmaf(x0, p1[f], fmaf(x1, p1[f + 1], d1));
        d2 = fmaf(x0, p2[f], fmaf(x1, p2[f + 1], d2));
    }
    for (int o = 16; o; o >>= 1) {
        d1 += __shfl_xor_sync(0xFFFFFFFFu, d1, o);
        d2 += __shfl_xor_sync(0xFFFFFFFFu, d2, o);
    }
    if (lane == 0) { s1[h * NN + row] = d1; s2[h * NN + row] = d2; }
}

// s for out layer 0 (fout=64, fp32)
__global__ void k_s(const float* __restrict__ Wh, const float* __restrict__ a, int fout,
                    float* __restrict__ s1, float* __restrict__ s2) {
    int gw = (blockIdx.x * blockDim.x + threadIdx.x) >> 5;
    int lane = threadIdx.x & 31;
    if (gw >= NN) return;
    const float* row = Wh + (long)gw * fout;
    float d1 = 0.f, d2 = 0.f;
    for (int f = lane; f < fout; f += 32) {
        float v = row[f];
        d1 += v * a[f];
        d2 += v * a[fout + f];
    }
    for (int o = 16; o; o >>= 1) {
        d1 += __shfl_xor_sync(0xFFFFFFFFu, d1, o);
        d2 += __shfl_xor_sync(0xFFFFFFFFu, d2, o);
    }
    if (lane == 0) { s1[gw] = d1; s2[gw] = d2; }
}

// per-head M = leaky(max s1 + max s2)
__global__ void k_max4(const float* __restrict__ s1, const float* __restrict__ s2,
                       float* __restrict__ Mp, int nheads) {
    int h = blockIdx.x;
    const float* a = s1 + (long)h * NN;
    const float* b = s2 + (long)h * NN;
    __shared__ float m1s[512], m2s[512];
    int t = threadIdx.x;
    float m1 = -1e30f, m2 = -1e30f;
    for (int i = t; i < NN; i += 512) { m1 = fmaxf(m1, a[i]); m2 = fmaxf(m2, b[i]); }
    m1s[t] = m1; m2s[t] = m2; __syncthreads();
    for (int s = 256; s; s >>= 1) {
        if (t < s) { m1s[t] = fmaxf(m1s[t], m1s[t + s]); m2s[t] = fmaxf(m2s[t], m2s[t + s]); }
        __syncthreads();
    }
    if (t == 0) Mp[h] = lrelu(m1s[0] + m2s[0]);
}

// ---------------- bf16 sparse aggregation (FOUT=256), slim inner loop --------
__global__ void __launch_bounds__(256) k_aggb(
    const __nv_bfloat16* __restrict__ WhbAll,
    const float* __restrict__ s1, const float* __restrict__ s2,
    const float* __restrict__ Mp,
    const int* __restrict__ rp, const int* __restrict__ ci,
    __nv_bfloat16* __restrict__ outBase, long headStride, int ostride) {
    int row = blockIdx.x;
    int h = blockIdx.y;
    const char* Wb = (const char*)WhbAll + (long)h * NN * 512;
    const float* s1h = s1 + (long)h * NN;
    const float* s2h = s2 + (long)h * NN;
    __nv_bfloat16* out = outBase + (long)h * headStride + (long)row * ostride;

    int tid = threadIdx.x;
    int tx = tid & 31;
    int ty = tid >> 5;

    __shared__ float    sw[258];
    __shared__ unsigned soff[258];
    __shared__ float    sacc[2048];
    __shared__ float    szw[8];

    float s1i = s1h[row];
    float M = Mp[h];
    int rs = rp[row], re = rp[row + 1];

    float acc0[8] = {0.f,0.f,0.f,0.f,0.f,0.f,0.f,0.f};
    float acc1[8] = {0.f,0.f,0.f,0.f,0.f,0.f,0.f,0.f};
    float z = 0.f;

    for (int base = rs; base < re; base += 256) {
        int n = min(256, re - base);
        __syncthreads();
        if (tid < n) {
            int j = ci[base + tid];
            soff[tid] = (unsigned)j << 9;
            float w = __expf(lrelu(s1i + s2h[j]) - M);
            sw[tid] = w;
            z += w;
        }
        if (tid < 2) { sw[n + tid] = 0.f; soff[n + tid] = 0u; }
        __syncthreads();
        unsigned lof = tx * 16;
        for (int t = 2 * ty; t < n; t += 16) {
            float w0 = sw[t], w1 = sw[t + 1];
            unsigned o0 = soff[t], o1 = soff[t + 1];
            uint4 v0 = *reinterpret_cast<const uint4*>(Wb + o0 + lof);
            uint4 v1 = *reinterpret_cast<const uint4*>(Wb + o1 + lof);
#define UNP(u, w, A, k0) \
            A[k0]   = fmaf(w, __uint_as_float((u) << 16),         A[k0]);   \
            A[k0+1] = fmaf(w, __uint_as_float((u) & 0xFFFF0000u), A[k0+1]);
            UNP(v0.x, w0, acc0, 0) UNP(v0.y, w0, acc0, 2)
            UNP(v0.z, w0, acc0, 4) UNP(v0.w, w0, acc0, 6)
            UNP(v1.x, w1, acc1, 0) UNP(v1.y, w1, acc1, 2)
            UNP(v1.z, w1, acc1, 4) UNP(v1.w, w1, acc1, 6)
#undef UNP
        }
    }
#pragma unroll
    for (int k = 0; k < 8; k++) acc0[k] += acc1[k];

    // z: warp reduce then per-warp slot
    for (int o = 16; o; o >>= 1) z += __shfl_xor_sync(0xFFFFFFFFu, z, o);
    if (tx == 0) szw[ty] = z;

    // feature reduce across 8 warps
    *reinterpret_cast<float4*>(&sacc[ty * 256 + tx * 8])     =
        make_float4(acc0[0], acc0[1], acc0[2], acc0[3]);
    *reinterpret_cast<float4*>(&sacc[ty * 256 + tx * 8 + 4]) =
        make_float4(acc0[4], acc0[5], acc0[6], acc0[7]);
    __syncthreads();
#pragma unroll
    for (int s = 4; s; s >>= 1) {
        if (ty < s) {
            float4* d0 = reinterpret_cast<float4*>(&sacc[ty * 256 + tx * 8]);
            float4* o0 = reinterpret_cast<float4*>(&sacc[(ty + s) * 256 + tx * 8]);
            float4 a = d0[0], b = o0[0];
            a.x += b.x; a.y += b.y; a.z += b.z; a.w += b.w; d0[0] = a;
            float4 c = d0[1], e = o0[1];
            c.x += e.x; c.y += e.y; c.z += e.z; c.w += e.w; d0[1] = c;
        }
        __syncthreads();
    }
    if (ty == 0) {
        float Z = szw[0] + szw[1] + szw[2] + szw[3] + szw[4] + szw[5] + szw[6] + szw[7];
        float inv = 1.0f / Z;
        float o[8];
#pragma unroll
        for (int k = 0; k < 8; k++) {
            float t = sacc[tx * 8 + k] * inv;
            o[k] = t > 0.f ? t : expm1f(t);   // elu
        }
        uint4 w;
        __nv_bfloat162 p;
        p = __float22bfloat162_rn(make_float2(o[0], o[1])); w.x = *(unsigned int*)&p;
        p = __float22bfloat162_rn(make_float2(o[2], o[3])); w.y = *(unsigned int*)&p;
        p = __float22bfloat162_rn(make_float2(o[4], o[5])); w.z = *(unsigned int*)&p;
        p = __float22bfloat162_rn(make_float2(o[6], o[7])); w.w = *(unsigned int*)&p;
        *reinterpret_cast<uint4*>(out + tx * 8) = w;
    }
}

// fp32 aggregation (FOUT=64, out layer 0, no elu)
__global__ void k_agg64(const float* __restrict__ Wh, const float* __restrict__ s1,
                        const float* __restrict__ s2, const float* __restrict__ Mp,
                        const int* __restrict__ rp, const int* __restrict__ ci,
                        float* __restrict__ out) {
    constexpr int TX = 16, TY = 16;
    int row = blockIdx.x;
    int tid = threadIdx.x;
    int tx = tid % TX, ty = tid / TX;
    __shared__ float sw[256];
    __shared__ int sj[256];
    __shared__ float4 sacc[256];
    __shared__ float sz[256];
    float s1i = s1[row];
    float M = Mp[0];
    int rs = rp[row], re = rp[row + 1];
    float4 acc = make_float4(0.f, 0.f, 0.f, 0.f);
    float z = 0.f;
    for (int base = rs; base < re; base += 256) {
        int n = min(256, re - base);
        __syncthreads();
        for (int t = tid; t < n; t += 256) {
            int j = ci[base + t];
            sj[t] = j;
            float w = __expf(lrelu(s1i + s2[j]) - M);
            sw[t] = w;
            z += w;
        }
        __syncthreads();
        for (int t = ty; t < n; t += TY) {
            float w = sw[t];
            float4 v = reinterpret_cast<const float4*>(Wh + (long)sj[t] * 64)[tx];
            acc.x += w * v.x; acc.y += w * v.y; acc.z += w * v.z; acc.w += w * v.w;
        }
    }
    sacc[tid] = acc; sz[tid] = z; __syncthreads();
    for (int s = 128; s; s >>= 1) { if (tid < s) sz[tid] += sz[tid + s]; __syncthreads(); }
    if (ty == 0) {
        float4 a = sacc[tx];
#pragma unroll
        for (int yy = 1; yy < TY; yy++) {
            float4 b = sacc[yy * TX + tx];
            a.x += b.x; a.y += b.y; a.z += b.z; a.w += b.w;
        }
        float inv = 1.0f / sz[0];
        *reinterpret_cast<float4*>(out + (long)row * 64 + tx * 4) =
            make_float4(a.x * inv, a.y * inv, a.z * inv, a.w * inv);
    }
}

// FOUT == 1 aggregation
__global__ void k_agg1(const float* __restrict__ whc, const float* __restrict__ s1,
                       const float* __restrict__ s2, const float* __restrict__ Mp,
                       const int* __restrict__ rp, const int* __restrict__ ci,
                       float* __restrict__ out) {
    int row = blockIdx.x, tid = threadIdx.x;
    __shared__ float sa[256], szz[256];
    float s1i = s1[row], M = Mp[0];
    int rs = rp[row], re = rp[row + 1];
    float acc = 0.f, z = 0.f;
    for (int e = rs + tid; e < re; e += 256) {
        int j = ci[e];
        float w = __expf(lrelu(s1i + s2[j]) - M);
        z += w;
        acc += w * whc[j];
    }
    sa[tid] = acc; szz[tid] = z; __syncthreads();
    for (int s = 128; s; s >>= 1) {
        if (tid < s) { sa[tid] += sa[tid + s]; szz[tid] += szz[tid + s]; }
        __syncthreads();
    }
    if (tid == 0) out[row] = sa[0] / szz[0];
}

__global__ void k_out1s(const float* __restrict__ h, const float* __restrict__ Wo1,
                        const float* __restrict__ ao1, float* __restrict__ whc,
                        float* __restrict__ s1, float* __restrict__ s2) {
    int gw = (blockIdx.x * blockDim.x + threadIdx.x) >> 5;
    int lane = threadIdx.x & 31;
    if (gw >= NN) return;
    float d = 0.f;
    for (int f = lane; f < 64; f += 32) d += h[(long)gw * 64 + f] * Wo1[f];
    for (int o = 16; o; o >>= 1) d += __shfl_xor_sync(0xFFFFFFFFu, d, o);
    if (lane == 0) { whc[gw] = d; s1[gw] = d * ao1[0]; s2[gw] = d * ao1[1]; }
}

// ---------------- bf16 tensor-core GEMM ----------------
__device__ __forceinline__ void ldsm4(unsigned& r0, unsigned& r1, unsigned& r2, unsigned& r3,
                                      unsigned addr) {
    asm volatile("ldmatrix.sync.aligned.m8n8.x4.shared.b16 {%0,%1,%2,%3}, [%4];"
                 : "=r"(r0), "=r"(r1), "=r"(r2), "=r"(r3) : "r"(addr));
}
__device__ __forceinline__ void ldsm4t(unsigned& r0, unsigned& r1, unsigned& r2, unsigned& r3,
                                       unsigned addr) {
    asm volatile("ldmatrix.sync.aligned.m8n8.x4.trans.shared.b16 {%0,%1,%2,%3}, [%4];"
                 : "=r"(r0), "=r"(r1), "=r"(r2), "=r"(r3) : "r"(addr));
}
__device__ __forceinline__ void mma16816(float* c, unsigned a0, unsigned a1, unsigned a2,
                                         unsigned a3, unsigned b0, unsigned b1) {
    asm volatile(
        "mma.sync.aligned.m16n8k16.row.col.f32.bf16.bf16.f32 "
        "{%0,%1,%2,%3},{%4,%5,%6,%7},{%8,%9},{%0,%1,%2,%3};"
        : "+f"(c[0]), "+f"(c[1]), "+f"(c[2]), "+f"(c[3])
        : "r"(a0), "r"(a1), "r"(a2), "r"(a3), "r"(b0), "r"(b1));
}

#define GA_ROWB 80
#define GB_ROWB 272
#define GA_BYTES (128 * GA_ROWB)

__global__ void __launch_bounds__(256, 2) k_bgemm(
    const __nv_bfloat16* __restrict__ A, const __nv_bfloat16* __restrict__ B,
    float* __restrict__ C, unsigned int* __restrict__ Cb,
    int M, int N, int K, long sA, long sB, long sC, long sCb) {
    __shared__ __align__(16) unsigned char sm[GA_BYTES + 32 * GB_ROWB];
    A += (long)blockIdx.z * sA;
    B += (long)blockIdx.z * sB;
    if (C) C += (long)blockIdx.z * sC;
    if (Cb) Cb += (long)blockIdx.z * sCb;

    int tid = threadIdx.x;
    int warp = tid >> 5, lane = tid & 31;
    int wm = warp & 3, wn = warp >> 2;
    int m0 = blockIdx.y * 128, n0 = blockIdx.x * 128;

    uint4* As4 = reinterpret_cast<uint4*>(sm);
    uint4* Bs4 = reinterpret_cast<uint4*>(sm + GA_BYTES);

    int ar = tid >> 2;
    int ac = tid & 3;
    int br = tid >> 4;
    int bc = tid & 15;
    bool bok = (n0 + bc * 8) < N;

    unsigned sA_base = (unsigned)__cvta_generic_to_shared(sm);
    unsigned sB_base = sA_base + GA_BYTES;
    int sub = lane >> 3, r = lane & 7;

    float acc[2][8][4] = {};
    int KT = K / 32;
    uint4 av0, av1, bv0, bv1;
    const uint4 zero4 = make_uint4(0, 0, 0, 0);

    av0 = reinterpret_cast<const uint4*>(A + (long)(m0 + ar) * K)[ac];
    av1 = reinterpret_cast<const uint4*>(A + (long)(m0 + ar + 64) * K)[ac];
    bv0 = bok ? *reinterpret_cast<const uint4*>(B + (long)br * N + n0 + bc * 8) : zero4;
    bv1 = bok ? *reinterpret_cast<const uint4*>(B + (long)(br + 16) * N + n0 + bc * 8) : zero4;

    for (int it = 0; it < KT; it++) {
        As4[ar * 5 + ac] = av0;
        As4[(ar + 64) * 5 + ac] = av1;
        Bs4[br * 17 + bc] = bv0;
        Bs4[(br + 16) * 17 + bc] = bv1;
        __syncthreads();

        if (it + 1 < KT) {
            int kof = (it + 1) * 32;
            av0 = reinterpret_cast<const uint4*>(A + (long)(m0 + ar) * K + kof)[ac];
            av1 = reinterpret_cast<const uint4*>(A + (long)(m0 + ar + 64) * K + kof)[ac];
            bv0 = bok ? *reinterpret_cast<const uint4*>(B + (long)(kof + br) * N + n0 + bc * 8) : zero4;
            bv1 = bok ? *reinterpret_cast<const uint4*>(B + (long)(kof + br + 16) * N + n0 + bc * 8) : zero4;
        }

#pragma unroll
        for (int ks = 0; ks < 2; ks++) {
            unsigned a[2][4];
#pragma unroll
            for (int i = 0; i < 2; i++) {
                unsigned addr = sA_base
                    + (unsigned)((wm * 32 + i * 16 + (sub & 1) * 8 + r) * GA_ROWB
                                 + ks * 32 + (sub >> 1) * 16);
                ldsm4(a[i][0], a[i][1], a[i][2], a[i][3], addr);
            }
            unsigned b[4][4];
#pragma unroll
            for (int j = 0; j < 4; j++) {
                unsigned addr = sB_base
                    + (unsigned)((ks * 16 + (sub & 1) * 8 + r) * GB_ROWB
                                 + (wn * 64 + j * 16 + (sub >> 1) * 8) * 2);
                ldsm4t(b[j][0], b[j][1], b[j][2], b[j][3], addr);
            }
#pragma unroll
            for (int i = 0; i < 2; i++) {
#pragma unroll
                for (int j = 0; j < 4; j++) {
                    mma16816(acc[i][2 * j],     a[i][0], a[i][1], a[i][2], a[i][3],
                             b[j][0], b[j][1]);
                    mma16816(acc[i][2 * j + 1], a[i][0], a[i][1], a[i][2], a[i][3],
                             b[j][2], b[j][3]);
                }
            }
        }
        __syncthreads();
    }

    int g = lane >> 2, ti = lane & 3;
#pragma unroll
    for (int i = 0; i < 2; i++) {
#pragma unroll
        for (int jj = 0; jj < 8; jj++) {
            int row = m0 + wm * 32 + i * 16 + g;
            int col = n0 + wn * 64 + jj * 8 + ti * 2;
            if (col < N) {
                float* c = acc[i][jj];
                if (C) {
                    *reinterpret_cast<float2*>(C + (long)row * N + col) = make_float2(c[0], c[1]);
                    *reinterpret_cast<float2*>(C + (long)(row + 8) * N + col) = make_float2(c[2], c[3]);
                }
                if (Cb) {
                    __nv_bfloat162 p0 = __float22bfloat162_rn(make_float2(c[0], c[1]));
                    __nv_bfloat162 p1 = __float22bfloat162_rn(make_float2(c[2], c[3]));
                    Cb[((long)row * N + col) >> 1] = *reinterpret_cast<unsigned int*>(&p0);
                    Cb[((long)(row + 8) * N + col) >> 1] = *reinterpret_cast<unsigned int*>(&p1);
                }
            }
        }
    }
}

// ---------------- final degree MLP ----------------
__global__ void k_mlp(const float* __restrict__ hout, const float* __restrict__ dv,
                      const float* __restrict__ dW, const float* __restrict__ dW0,
                      const float* __restrict__ dW1, const float* __restrict__ dW01,
                      const float* __restrict__ dW2, const float* __restrict__ dW02,
                      const float* __restrict__ dV, const float* __restrict__ dV0,
                      float* __restrict__ out) {
    int i = blockIdx.x * blockDim.x + threadIdx.x;
    if (i >= NN) return;
    float hv = hout[i];
    float x0 = hv > 0.f ? hv : expm1f(hv);
    float x1 = dv[i];
    float h0[10];
#pragma unroll
    for (int k = 0; k < 10; k++)
        h0[k] = lrelu(x0 * dW[k] + x1 * dW[10 + k] + dW0[k]);
    float h1[20];
#pragma unroll
    for (int k = 0; k < 20; k++) {
        float t = dW01[k];
#pragma unroll
        for (int j = 0; j < 10; j++) t += h0[j] * dW1[j * 20 + k];
        h1[k] = lrelu(t);
    }
    float h2[10];
#pragma unroll
    for (int k = 0; k < 10; k++) {
        float t = dW02[k];
#pragma unroll
        for (int j = 0; j < 20; j++) t += h1[j] * dW2[j * 10 + k];
        h2[k] = lrelu(t);
    }
    float o = dV0[0];
#pragma unroll
    for (int j = 0; j < 10; j++) o += h2[j] * dV[j];
    out[i] = lrelu(o);
}

// ---------------- launch ----------------
extern "C" void kernel_launch(void* const* d_in, const int* in_sizes, int n_in,
                              void* d_out, int out_size) {
    const float* x     = (const float*)d_in[0];
    const float* adj   = (const float*)d_in[1];
    const int*   obs   = (const int*)d_in[2];
    const float* s_mat = (const float*)d_in[3];
    const float* theta = (const float*)d_in[4];
    const float* Wh0   = (const float*)d_in[5];
    const float* ah0   = (const float*)d_in[6];
    const float* Wh1   = (const float*)d_in[7];
    const float* ah1   = (const float*)d_in[8];
    const float* Wo0   = (const float*)d_in[9];
    const float* ao0   = (const float*)d_in[10];
    const float* Wo1   = (const float*)d_in[11];
    const float* ao1   = (const float*)d_in[12];
    const float* dW    = (const float*)d_in[13];
    const float* dW0   = (const float*)d_in[14];
    const float* dW1   = (const float*)d_in[15];
    const float* dW01  = (const float*)d_in[16];
    const float* dW2   = (const float*)d_in[17];
    const float* dW02  = (const float*)d_in[18];
    const float* dV    = (const float*)d_in[19];
    const float* dV0   = (const float*)d_in[20];
    float* out = (float*)d_out;

    float* fa = nullptr;
    int*   ia = nullptr;
    cudaGetSymbolAddress((void**)&fa, g_farena);
    cudaGetSymbolAddress((void**)&ia, g_iarena);

    float* P0   = fa + OFF_P0;
    float* P1   = fa + OFF_P1;
    float* oWh  = fa + OFF_OWH;
    float* ho0  = fa + OFF_HO0;
    float* whc  = fa + OFF_WHC;
    float* hout = fa + OFF_HOUT;
    float* s1   = fa + OFF_S1;
    float* s2   = fa + OFF_S2;
    float* Mp   = fa + OFF_M;
    float* dv   = fa + OFF_DV;
    __nv_bfloat16* Whb   = (__nv_bfloat16*)(fa + OFF_WHB);
    __nv_bfloat16* hinb  = (__nv_bfloat16*)(fa + OFF_HINB);
    __nv_bfloat16* h1bb  = (__nv_bfloat16*)(fa + OFF_H1B);
    __nv_bfloat16* hcatb = (__nv_bfloat16*)(fa + OFF_HCATB);
    __nv_bfloat16* W0b   = (__nv_bfloat16*)(fa + OFF_W0B);
    __nv_bfloat16* W1b   = (__nv_bfloat16*)(fa + OFF_W1B);
    __nv_bfloat16* Wo0b  = (__nv_bfloat16*)(fa + OFF_WO0B);
    int* cnt = ia + OFF_CNT;
    int* rp  = ia + OFF_RP;
    int* ci  = ia + OFF_CI;

    const long NM = (long)NN * 256;

    // CSR (launches 1-3)
    k_count<<<NN, 256>>>(adj, cnt);
    k_scan<<<1, 1024>>>(cnt, rp);
    k_fill<<<NN, 256>>>(adj, rp, ci);

    // launch 4: ncu PROBE — representative k_aggb on fresh CSR + steady-state data.
    // Writes only to h1bb head-0 rows 0..1023, which is fully overwritten by the
    // real L0 aggregation below before any consumer reads it.
    k_aggb<<<dim3(1024, 1), 256>>>(Whb, s1, s2, Mp, rp, ci, h1bb, NM, 256);

    // degree vector
    k_rowsum<<<NN, 256>>>(s_mat, dv);

    // bf16 conversions + merged input + P projections
    k_mergeb<<<2048, 256>>>((const float4*)x, obs, (const float4*)theta, (uint2*)hinb);
    k_cvt<<<512, 256>>>((const float4*)Wh0, (uint2*)W0b, 131072);
    k_cvt<<<256, 256>>>((const float4*)Wh1, (uint2*)W1b, 65536);
    k_cvt<<<64, 256>>>((const float4*)Wo0, (uint2*)Wo0b, 16384);
    k_wa<<<dim3(128, 4), 256>>>(Wh0, ah0, P0, 512);
    k_wa<<<dim3(64, 4), 256>>>(Wh1, ah1, P1, 256);

    // ---- head layer 0 ----
    k_bgemm<<<dim3(2, 32, 4), 256>>>(hinb, W0b, nullptr, (unsigned int*)Whb,
                                     NN, 256, 512, 0L, 512L * 256, 0L, (long)NN * 128);
    k_sb<<<2048, 256>>>(hinb, 0L, P0, 512, s1, s2);
    k_max4<<<4, 512>>>(s1, s2, Mp, 4);
    k_aggb<<<dim3(NN, 4), 256>>>(Whb, s1, s2, Mp, rp, ci, h1bb, NM, 256);

    // ---- head layer 1 ----
    k_bgemm<<<dim3(2, 32, 4), 256>>>(h1bb, W1b, nullptr, (unsigned int*)Whb,
                                     NN, 256, 256, NM, 256L * 256, 0L, (long)NN * 128);
    k_sb<<<2048, 256>>>(h1bb, NM, P1, 256, s1, s2);
    k_max4<<<4, 512>>>(s1, s2, Mp, 4);
    k_aggb<<<dim3(NN, 4), 256>>>(Whb, s1, s2, Mp, rp, ci, hcatb, 256L, 1024);

    // ---- output layer 0 ----
    k_bgemm<<<dim3(1, 32, 1), 256>>>(hcatb, Wo0b, oWh, nullptr,
                                     NN, 64, 1024, 0L, 0L, 0L, 0L);
    k_s<<<512, 256>>>(oWh, ao0, 64, s1, s2);
    k_max4<<<1, 512>>>(s1, s2, Mp, 1);
    k_agg64<<<NN, 256>>>(oWh, s1, s2, Mp, rp, ci, ho0);

    // ---- output layer 1 ----
    k_out1s<<<512, 256>>>(ho0, Wo1, ao1, whc, s1, s2);
    k_max4<<<1, 512>>>(s1, s2, Mp, 1);
    k_agg1<<<NN, 256>>>(whc, s1, s2, Mp, rp, ci, hout);

    // ---- elu + degree MLP ----
    k_mlp<<<16, 256>>>(hout, dv, dW, dW0, dW1, dW01, dW2, dW02, dV, dV0, out);
}